// round 6
// baseline (speedup 1.0000x reference)
#include <cuda_runtime.h>
#include <cuda_bf16.h>
#include <math.h>
#include <stdint.h>

#define Nn 8192
#define Dd 512
#define KDIM 512
#define NHEADS 8
#define HDIM 64
#define TOPK 16

// ---------------- scratch (static device globals; no allocation) -------------
__device__ float g_seq[2 * Nn * Dd];
__device__ float g_qkv[2 * Nn * 3 * Dd];
__device__ float g_att[2 * Nn * Dd];
__device__ float g_S[(size_t)Nn * Nn];
__device__ float g_hidden[Nn * (Dd / 2)];
__device__ uint16_t g_ah[2 * Nn * Dd], g_al[2 * Nn * Dd];   // activations hi/lo
__device__ uint16_t g_bh[3 * Dd * Dd], g_bl[3 * Dd * Dd];   // weights hi/lo
__device__ uint16_t g_fh[Nn * Dd], g_fl[Nn * Dd];           // fused hi/lo

// ============================ PTX helpers ====================================
__device__ __forceinline__ uint32_t smem_u32(const void* p) {
    uint32_t a;
    asm("{ .reg .u64 t; cvta.to.shared.u64 t, %1; cvt.u32.u64 %0, t; }" : "=r"(a) : "l"(p));
    return a;
}
__device__ __forceinline__ void cp16(uint32_t dst, const void* src) {
    asm volatile("cp.async.cg.shared.global [%0], [%1], 16;" :: "r"(dst), "l"(src) : "memory");
}
__device__ __forceinline__ void cp_commit() {
    asm volatile("cp.async.commit_group;" ::: "memory");
}
template <int N> __device__ __forceinline__ void cp_wait() {
    asm volatile("cp.async.wait_group %0;" :: "n"(N) : "memory");
}
__device__ __forceinline__ void ldsm4(uint32_t* r, uint32_t a) {
    asm volatile("ldmatrix.sync.aligned.m8n8.x4.shared.b16 {%0,%1,%2,%3}, [%4];"
                 : "=r"(r[0]), "=r"(r[1]), "=r"(r[2]), "=r"(r[3]) : "r"(a));
}
__device__ __forceinline__ void mma16816(float* c, const uint32_t* a, uint32_t b0, uint32_t b1) {
    asm volatile("mma.sync.aligned.m16n8k16.row.col.f32.bf16.bf16.f32 "
                 "{%0,%1,%2,%3}, {%4,%5,%6,%7}, {%8,%9}, {%0,%1,%2,%3};"
                 : "+f"(c[0]), "+f"(c[1]), "+f"(c[2]), "+f"(c[3])
                 : "r"(a[0]), "r"(a[1]), "r"(a[2]), "r"(a[3]), "r"(b0), "r"(b1));
}

// ======================= warp-MMA NT GEMM (bf16 hi/lo, fp32 acc) =============
// C[M,N] = sum over 3 passes: Ah*Bh^T, Ah*Bl^T, Al*Bh^T.  K == 512 everywhere.
// Tile 128x128, BK=32, 3-stage cp.async pipeline (1 barrier per chunk).
template <int RELU, int HAS_BIAS>
__global__ __launch_bounds__(256, 2) void tgemm(
    const uint16_t* __restrict__ Ahp, const uint16_t* __restrict__ Alp,
    const uint16_t* __restrict__ Bhp, const uint16_t* __restrict__ Blp,
    const float* __restrict__ bias, float* __restrict__ C, int ldc)
{
    __shared__ uint16_t sA[3][128 * 32];
    __shared__ uint16_t sB[3][128 * 32];

    const int tid = threadIdx.x;
    const int lane = tid & 31, wid = tid >> 5;
    const int wm = wid & 3;
    const int wn = wid >> 2;
    const int bm = blockIdx.y * 128, bn = blockIdx.x * 128;

    uint32_t saB[3], sbB[3];
#pragma unroll
    for (int i = 0; i < 3; i++) { saB[i] = smem_u32(&sA[i][0]); sbB[i] = smem_u32(&sB[i][0]); }

    const uint16_t* Asrc[3] = { Ahp, Ahp, Alp };
    const uint16_t* Bsrc[3] = { Bhp, Blp, Bhp };
    const int CPP = KDIM / 32;
    const int NCHK = 3 * CPP;

    uint32_t lsw[2]; size_t lsrc[2];
#pragma unroll
    for (int i = 0; i < 2; i++) {
        int s = tid + 256 * i;
        int r = s >> 2, c = s & 3;
        lsw[i] = r * 64 + (((c ^ ((r >> 1) & 3))) << 4);
        lsrc[i] = (size_t)r * KDIM + c * 8;
    }

    uint32_t offA[2][2], offB[2][4];
#pragma unroll
    for (int kk = 0; kk < 2; kk++) {
#pragma unroll
        for (int f = 0; f < 2; f++) {
            int r = wm * 32 + f * 16 + (lane & 15);
            int c = kk * 2 + (lane >> 4);
            offA[kk][f] = r * 64 + (((c ^ ((r >> 1) & 3))) << 4);
        }
#pragma unroll
        for (int g = 0; g < 4; g++) {
            int r = wn * 64 + g * 16 + (lane & 7) + ((lane >> 4) << 3);
            int c = kk * 2 + ((lane >> 3) & 1);
            offB[kk][g] = r * 64 + (((c ^ ((r >> 1) & 3))) << 4);
        }
    }

    float acc[2][8][4];
#pragma unroll
    for (int f = 0; f < 2; f++)
#pragma unroll
        for (int g = 0; g < 8; g++)
#pragma unroll
            for (int j = 0; j < 4; j++) acc[f][g][j] = 0.f;

    auto load_chunk = [&](int c, int buf) {
        const int pass = c / CPP;
        const int k0 = (c % CPP) * 32;
        const uint16_t* A = Asrc[pass];
        const uint16_t* B = Bsrc[pass];
        const uint32_t da = saB[buf], db = sbB[buf];
#pragma unroll
        for (int i = 0; i < 2; i++) {
            cp16(da + lsw[i], A + (size_t)bm * KDIM + k0 + lsrc[i]);
            cp16(db + lsw[i], B + (size_t)bn * KDIM + k0 + lsrc[i]);
        }
        cp_commit();
    };

    load_chunk(0, 0);
    load_chunk(1, 1);

    for (int c = 0; c < NCHK; c++) {
        if (c + 1 < NCHK) cp_wait<1>(); else cp_wait<0>();
        __syncthreads();
        if (c + 2 < NCHK) load_chunk(c + 2, (c + 2) % 3);

        const uint32_t da = saB[c % 3], db = sbB[c % 3];
#pragma unroll
        for (int kk = 0; kk < 2; kk++) {
            uint32_t ra[2][4], rb[4][4];
#pragma unroll
            for (int f = 0; f < 2; f++) ldsm4(ra[f], da + offA[kk][f]);
#pragma unroll
            for (int g = 0; g < 4; g++) ldsm4(rb[g], db + offB[kk][g]);
#pragma unroll
            for (int f = 0; f < 2; f++)
#pragma unroll
                for (int g = 0; g < 4; g++) {
                    mma16816(acc[f][2 * g + 0], ra[f], rb[g][0], rb[g][1]);
                    mma16816(acc[f][2 * g + 1], ra[f], rb[g][2], rb[g][3]);
                }
        }
    }

    const int col0 = bn + wn * 64 + (lane & 3) * 2;
#pragma unroll
    for (int f = 0; f < 2; f++) {
        const int row0 = bm + wm * 32 + f * 16 + (lane >> 2);
#pragma unroll
        for (int g = 0; g < 8; g++) {
            const int col = col0 + g * 8;
            float b0 = 0.f, b1 = 0.f;
            if (HAS_BIAS) { b0 = bias[col]; b1 = bias[col + 1]; }
            float2 v0, v1;
            v0.x = acc[f][g][0] + b0; v0.y = acc[f][g][1] + b1;
            v1.x = acc[f][g][2] + b0; v1.y = acc[f][g][3] + b1;
            if (RELU) {
                v0.x = fmaxf(v0.x, 0.f); v0.y = fmaxf(v0.y, 0.f);
                v1.x = fmaxf(v1.x, 0.f); v1.y = fmaxf(v1.y, 0.f);
            }
            *(float2*)(C + (size_t)row0 * ldc + col) = v0;
            *(float2*)(C + (size_t)(row0 + 8) * ldc + col) = v1;
        }
    }
}

// ============== symmetric variant: S = F*F^T, upper-triangle blocks ==========
__global__ __launch_bounds__(256, 2) void tgemm_sym(
    const uint16_t* __restrict__ Fh, const uint16_t* __restrict__ Fl,
    float* __restrict__ C)
{
    __shared__ __align__(16) uint8_t smraw[49152];       // 3-stage A+B bufs
    float* smT = (float*)smraw;                          // reused in epilogue

    const int tid = threadIdx.x;
    const int lane = tid & 31, wid = tid >> 5;
    const int wm = wid & 3;
    const int wn = wid >> 2;

    int t = blockIdx.x;
    int bj = (int)((sqrtf(8.f * t + 1.f) - 1.f) * 0.5f);
    while ((bj + 1) * (bj + 2) / 2 <= t) bj++;
    while (bj * (bj + 1) / 2 > t) bj--;
    int bi = t - bj * (bj + 1) / 2;
    const int bm = bi * 128, bn = bj * 128;

    uint32_t saB[3], sbB[3];
#pragma unroll
    for (int i = 0; i < 3; i++) {
        saB[i] = smem_u32(smraw + i * 8192);
        sbB[i] = smem_u32(smraw + 24576 + i * 8192);
    }

    const uint16_t* Asrc[3] = { Fh, Fh, Fl };
    const uint16_t* Bsrc[3] = { Fh, Fl, Fh };
    const int CPP = KDIM / 32;
    const int NCHK = 3 * CPP;

    uint32_t lsw[2]; size_t lsrc[2];
#pragma unroll
    for (int i = 0; i < 2; i++) {
        int s = tid + 256 * i;
        int r = s >> 2, c = s & 3;
        lsw[i] = r * 64 + (((c ^ ((r >> 1) & 3))) << 4);
        lsrc[i] = (size_t)r * KDIM + c * 8;
    }

    uint32_t offA[2][2], offB[2][4];
#pragma unroll
    for (int kk = 0; kk < 2; kk++) {
#pragma unroll
        for (int f = 0; f < 2; f++) {
            int r = wm * 32 + f * 16 + (lane & 15);
            int c = kk * 2 + (lane >> 4);
            offA[kk][f] = r * 64 + (((c ^ ((r >> 1) & 3))) << 4);
        }
#pragma unroll
        for (int g = 0; g < 4; g++) {
            int r = wn * 64 + g * 16 + (lane & 7) + ((lane >> 4) << 3);
            int c = kk * 2 + ((lane >> 3) & 1);
            offB[kk][g] = r * 64 + (((c ^ ((r >> 1) & 3))) << 4);
        }
    }

    float acc[2][8][4];
#pragma unroll
    for (int f = 0; f < 2; f++)
#pragma unroll
        for (int g = 0; g < 8; g++)
#pragma unroll
            for (int j = 0; j < 4; j++) acc[f][g][j] = 0.f;

    auto load_chunk = [&](int c, int buf) {
        const int pass = c / CPP;
        const int k0 = (c % CPP) * 32;
        const uint16_t* A = Asrc[pass];
        const uint16_t* B = Bsrc[pass];
        const uint32_t da = saB[buf], db = sbB[buf];
#pragma unroll
        for (int i = 0; i < 2; i++) {
            cp16(da + lsw[i], A + (size_t)bm * KDIM + k0 + lsrc[i]);
            cp16(db + lsw[i], B + (size_t)bn * KDIM + k0 + lsrc[i]);
        }
        cp_commit();
    };

    load_chunk(0, 0);
    load_chunk(1, 1);

    for (int c = 0; c < NCHK; c++) {
        if (c + 1 < NCHK) cp_wait<1>(); else cp_wait<0>();
        __syncthreads();
        if (c + 2 < NCHK) load_chunk(c + 2, (c + 2) % 3);

        const uint32_t da = saB[c % 3], db = sbB[c % 3];
#pragma unroll
        for (int kk = 0; kk < 2; kk++) {
            uint32_t ra[2][4], rb[4][4];
#pragma unroll
            for (int f = 0; f < 2; f++) ldsm4(ra[f], da + offA[kk][f]);
#pragma unroll
            for (int g = 0; g < 4; g++) ldsm4(rb[g], db + offB[kk][g]);
#pragma unroll
            for (int f = 0; f < 2; f++)
#pragma unroll
                for (int g = 0; g < 4; g++) {
                    mma16816(acc[f][2 * g + 0], ra[f], rb[g][0], rb[g][1]);
                    mma16816(acc[f][2 * g + 1], ra[f], rb[g][2], rb[g][3]);
                }
        }
    }

    // normal (upper) tile write
    const int col0 = bn + wn * 64 + (lane & 3) * 2;
#pragma unroll
    for (int f = 0; f < 2; f++) {
        const int row0 = bm + wm * 32 + f * 16 + (lane >> 2);
#pragma unroll
        for (int g = 0; g < 8; g++) {
            const int col = col0 + g * 8;
            float2 v0, v1;
            v0.x = acc[f][g][0]; v0.y = acc[f][g][1];
            v1.x = acc[f][g][2]; v1.y = acc[f][g][3];
            *(float2*)(C + (size_t)row0 * Nn + col) = v0;
            *(float2*)(C + (size_t)(row0 + 8) * Nn + col) = v1;
        }
    }

    // mirrored (lower) tile write via smem transpose, coalesced
    if (bi != bj) {
#pragma unroll
        for (int cc = 0; cc < 2; cc++) {
            __syncthreads();
            float* buf = smT + wn * (32 * 128);
#pragma unroll
            for (int gl = 0; gl < 4; gl++) {
                const int g = cc * 4 + gl;
                const int cl = gl * 8 + (lane & 3) * 2;
#pragma unroll
                for (int f = 0; f < 2; f++) {
                    const int r = wm * 32 + f * 16 + (lane >> 2);
                    buf[cl * 128 + r]           = acc[f][g][0];
                    buf[(cl + 1) * 128 + r]     = acc[f][g][1];
                    buf[cl * 128 + r + 8]       = acc[f][g][2];
                    buf[(cl + 1) * 128 + r + 8] = acc[f][g][3];
                }
            }
            __syncthreads();
            for (int idx = tid; idx < 64 * 32; idx += 256) {
                const int rr = idx >> 5;
                const int sg = idx & 31;
                const int b2 = rr >> 5;
                const int cl = rr & 31;
                const int cAbs = bn + b2 * 64 + cc * 32 + cl;
                float4 v = *(float4*)(smT + b2 * (32 * 128) + cl * 128 + sg * 4);
                *(float4*)(C + (size_t)cAbs * Nn + bm + sg * 4) = v;
            }
        }
    }
}

// ---------------- fp32 -> (hi, lo) bf16 split --------------------------------
__global__ void split_kernel(const float* __restrict__ x, uint16_t* __restrict__ hi,
                             uint16_t* __restrict__ lo, int n4)
{
    int i = blockIdx.x * blockDim.x + threadIdx.x;
    if (i >= n4) return;
    float4 v = ((const float4*)x)[i];
    __nv_bfloat16 h0 = __float2bfloat16(v.x), h1 = __float2bfloat16(v.y);
    __nv_bfloat16 h2 = __float2bfloat16(v.z), h3 = __float2bfloat16(v.w);
    __nv_bfloat16 l0 = __float2bfloat16(v.x - __bfloat162float(h0));
    __nv_bfloat16 l1 = __float2bfloat16(v.y - __bfloat162float(h1));
    __nv_bfloat16 l2 = __float2bfloat16(v.z - __bfloat162float(h2));
    __nv_bfloat16 l3 = __float2bfloat16(v.w - __bfloat162float(h3));
    ushort4 hv, lv;
    hv.x = __bfloat16_as_ushort(h0); hv.y = __bfloat16_as_ushort(h1);
    hv.z = __bfloat16_as_ushort(h2); hv.w = __bfloat16_as_ushort(h3);
    lv.x = __bfloat16_as_ushort(l0); lv.y = __bfloat16_as_ushort(l1);
    lv.z = __bfloat16_as_ushort(l2); lv.w = __bfloat16_as_ushort(l3);
    ((ushort4*)hi)[i] = hv;
    ((ushort4*)lo)[i] = lv;
}

// ---------------- LayerNorm -> bf16 hi/lo directly ---------------------------
__global__ void ln_kernel(const float* __restrict__ g0, const float* __restrict__ be0,
                          const float* __restrict__ g1, const float* __restrict__ be1)
{
    int row = blockIdx.x;
    const float* x = g_seq + (size_t)row * Dd;
    int tid = threadIdx.x;
    float v0 = x[tid], v1 = x[tid + 256];
    __shared__ float rs[256], rq[256];
    rs[tid] = v0 + v1;
    rq[tid] = v0 * v0 + v1 * v1;
    __syncthreads();
    for (int st = 128; st > 0; st >>= 1) {
        if (tid < st) { rs[tid] += rs[tid + st]; rq[tid] += rq[tid + st]; }
        __syncthreads();
    }
    float mean = rs[0] * (1.f / Dd);
    float var = rq[0] * (1.f / Dd) - mean * mean;
    float inv = rsqrtf(var + 1e-5f);
    const float* gg = (row & 1) ? g1 : g0;
    const float* bb = (row & 1) ? be1 : be0;
    float y0 = (v0 - mean) * inv * gg[tid] + bb[tid];
    float y1 = (v1 - mean) * inv * gg[tid + 256] + bb[tid + 256];
    size_t base = (size_t)row * Dd;
    __nv_bfloat16 h0 = __float2bfloat16(y0), h1 = __float2bfloat16(y1);
    g_ah[base + tid]       = __bfloat16_as_ushort(h0);
    g_ah[base + tid + 256] = __bfloat16_as_ushort(h1);
    g_al[base + tid]       = __bfloat16_as_ushort(__float2bfloat16(y0 - __bfloat162float(h0)));
    g_al[base + tid + 256] = __bfloat16_as_ushort(__float2bfloat16(y1 - __bfloat162float(h1)));
}

// ---------------- 2-token multihead attention -> ctx hi/lo -------------------
__global__ void attn_kernel()
{
    int gt = blockIdx.x * blockDim.x + threadIdx.x;
    int gw = gt >> 5, lane = gt & 31;
    if (gw >= Nn * NHEADS) return;
    int node = gw >> 3, h = gw & 7;
    const float* base = g_qkv + (size_t)node * 2 * (3 * Dd);
    int d0 = lane * 2;
    float q[2][2], k[2][2], v[2][2];
#pragma unroll
    for (int t = 0; t < 2; t++) {
        const float* r = base + t * (3 * Dd) + h * HDIM;
        float2 qq = *(const float2*)(r + d0);
        float2 kk = *(const float2*)(r + Dd + d0);
        float2 vv = *(const float2*)(r + 2 * Dd + d0);
        q[t][0] = qq.x; q[t][1] = qq.y;
        k[t][0] = kk.x; k[t][1] = kk.y;
        v[t][0] = vv.x; v[t][1] = vv.y;
    }
    float s[2][2];
#pragma unroll
    for (int qi = 0; qi < 2; qi++)
#pragma unroll
        for (int ki = 0; ki < 2; ki++)
            s[qi][ki] = q[qi][0] * k[ki][0] + q[qi][1] * k[ki][1];
#pragma unroll
    for (int o = 16; o > 0; o >>= 1)
#pragma unroll
        for (int qi = 0; qi < 2; qi++)
#pragma unroll
            for (int ki = 0; ki < 2; ki++)
                s[qi][ki] += __shfl_xor_sync(0xffffffffu, s[qi][ki], o);
    const float scale = 0.125f;
#pragma unroll
    for (int qi = 0; qi < 2; qi++) {
        float a0 = s[qi][0] * scale, a1 = s[qi][1] * scale;
        float m = fmaxf(a0, a1);
        float e0 = expf(a0 - m), e1 = expf(a1 - m);
        float inv = 1.f / (e0 + e1);
        float w0 = e0 * inv, w1 = e1 * inv;
        float o0 = w0 * v[0][0] + w1 * v[1][0];
        float o1 = w0 * v[0][1] + w1 * v[1][1];
        size_t off = (size_t)(node * 2 + qi) * Dd + h * HDIM + d0;
        __nv_bfloat16 h0 = __float2bfloat16(o0), h1 = __float2bfloat16(o1);
        ushort2 hv, lv;
        hv.x = __bfloat16_as_ushort(h0); hv.y = __bfloat16_as_ushort(h1);
        lv.x = __bfloat16_as_ushort(__float2bfloat16(o0 - __bfloat162float(h0)));
        lv.y = __bfloat16_as_ushort(__float2bfloat16(o1 - __bfloat162float(h1)));
        *(ushort2*)(g_ah + off) = hv;
        *(ushort2*)(g_al + off) = lv;
    }
}

// ---------------- mean over the 2 tokens -> fused hi/lo ----------------------
__global__ void mean_kernel()
{
    int i = blockIdx.x * blockDim.x + threadIdx.x;
    if (i >= Nn * Dd / 4) return;
    int e0 = i * 4;
    int node = e0 / Dd, d = e0 - node * Dd;
    const float* r0 = g_att + (size_t)(node * 2) * Dd + d;
    const float* r1 = g_att + (size_t)(node * 2 + 1) * Dd + d;
    float4 a = *(const float4*)r0, b = *(const float4*)r1;
    float f0 = 0.5f * (a.x + b.x), f1 = 0.5f * (a.y + b.y);
    float f2 = 0.5f * (a.z + b.z), f3 = 0.5f * (a.w + b.w);
    __nv_bfloat16 h0 = __float2bfloat16(f0), h1 = __float2bfloat16(f1);
    __nv_bfloat16 h2 = __float2bfloat16(f2), h3 = __float2bfloat16(f3);
    ushort4 hv, lv;
    hv.x = __bfloat16_as_ushort(h0); hv.y = __bfloat16_as_ushort(h1);
    hv.z = __bfloat16_as_ushort(h2); hv.w = __bfloat16_as_ushort(h3);
    lv.x = __bfloat16_as_ushort(__float2bfloat16(f0 - __bfloat162float(h0)));
    lv.y = __bfloat16_as_ushort(__float2bfloat16(f1 - __bfloat162float(h1)));
    lv.z = __bfloat16_as_ushort(__float2bfloat16(f2 - __bfloat162float(h2)));
    lv.w = __bfloat16_as_ushort(__float2bfloat16(f3 - __bfloat162float(h3)));
    ((ushort4*)g_fh)[i] = hv;
    ((ushort4*)g_fl)[i] = lv;
}

// ---------------- per-row softmax stats + top-16 + scatter into H -----------
// Shuffle-based block reductions: 2 barriers per argmax pass instead of 8.
__global__ void topk_kernel(float* __restrict__ Hout)
{
    int row = blockIdx.x;
    extern __shared__ float sh[];                 // Nn floats
    __shared__ float swv[8];
    __shared__ int swi[8];
    __shared__ float s_bcast;
    __shared__ float topv[TOPK];
    __shared__ int topi[TOPK];
    const float* srow = g_S + (size_t)row * Nn;
    int tid = threadIdx.x;
    int lane = tid & 31, wid = tid >> 5;

    // pass 1: load + row max
    float lmax = -INFINITY;
    for (int j = tid; j < Nn; j += 256) {
        float v = srow[j];
        sh[j] = v;
        lmax = fmaxf(lmax, v);
    }
#pragma unroll
    for (int o = 16; o > 0; o >>= 1)
        lmax = fmaxf(lmax, __shfl_xor_sync(0xffffffffu, lmax, o));
    if (lane == 0) swv[wid] = lmax;
    __syncthreads();
    if (tid == 0) {
        float m = swv[0];
#pragma unroll
        for (int w = 1; w < 8; w++) m = fmaxf(m, swv[w]);
        s_bcast = m;
    }
    __syncthreads();
    const float rmax = s_bcast;

    // pass 2: sum of exp
    float lsum = 0.f;
    for (int j = tid; j < Nn; j += 256) lsum += expf(sh[j] - rmax);
#pragma unroll
    for (int o = 16; o > 0; o >>= 1)
        lsum += __shfl_xor_sync(0xffffffffu, lsum, o);
    if (lane == 0) swv[wid] = lsum;
    __syncthreads();
    if (tid == 0) {
        float s = 0.f;
#pragma unroll
        for (int w = 0; w < 8; w++) s += swv[w];
        s_bcast = 1.f / s;
    }
    __syncthreads();
    const float rinv = s_bcast;

    // 16 argmax passes, shuffle-reduced
    for (int kk = 0; kk < TOPK; kk++) {
        float lm = -INFINITY; int li = 0x7fffffff;
        for (int j = tid; j < Nn; j += 256) {
            float v = sh[j];
            if (v > lm) { lm = v; li = j; }
        }
#pragma unroll
        for (int o = 16; o > 0; o >>= 1) {
            float ov = __shfl_xor_sync(0xffffffffu, lm, o);
            int oi = __shfl_xor_sync(0xffffffffu, li, o);
            if (ov > lm || (ov == lm && oi < li)) { lm = ov; li = oi; }
        }
        if (lane == 0) { swv[wid] = lm; swi[wid] = li; }
        __syncthreads();
        if (tid == 0) {
            float bv = swv[0]; int bi2 = swi[0];
#pragma unroll
            for (int w = 1; w < 8; w++) {
                if (swv[w] > bv || (swv[w] == bv && swi[w] < bi2)) { bv = swv[w]; bi2 = swi[w]; }
            }
            topv[kk] = bv;
            topi[kk] = bi2;
            sh[bi2] = -INFINITY;
        }
        __syncthreads();
    }

    if (tid == 0) {
        Hout[(size_t)row * Nn + row] = 1.0f;
#pragma unroll
        for (int kk = 0; kk < TOPK; kk++)
            Hout[(size_t)topi[kk] * Nn + row] = expf(topv[kk] - rmax) * rinv;
    }
}

__global__ void ew_kernel(const float* __restrict__ w2, const float* __restrict__ b2,
                          float* __restrict__ out)
{
    int gt = blockIdx.x * blockDim.x + threadIdx.x;
    int gw = gt >> 5, lane = gt & 31;
    if (gw >= Nn) return;
    const float* hrow = g_hidden + (size_t)gw * (Dd / 2);
    float s = 0.f;
    for (int j = lane; j < Dd / 2; j += 32) s += hrow[j] * w2[j];
#pragma unroll
    for (int o = 16; o > 0; o >>= 1) s += __shfl_xor_sync(0xffffffffu, s, o);
    if (lane == 0) {
        float v = s + b2[0];
        float sig = 1.f / (1.f + expf(-v));
        out[gw] = fmaxf(sig, 1e-8f);
    }
}

// ---------------- launch ------------------------------------------------------
static void do_split(const float* src, uint16_t* hi, uint16_t* lo, size_t n)
{
    int n4 = (int)(n / 4);
    split_kernel<<<(n4 + 255) / 256, 256>>>(src, hi, lo, n4);
}

extern "C" void kernel_launch(void* const* d_in, const int* in_sizes, int n_in,
                              void* d_out, int out_size)
{
    const float* x0    = (const float*)d_in[0];
    const float* x1    = (const float*)d_in[1];
    const float* w_p0  = (const float*)d_in[2];
    const float* b_p0  = (const float*)d_in[3];
    const float* gg0   = (const float*)d_in[4];
    const float* be0   = (const float*)d_in[5];
    const float* w_p1  = (const float*)d_in[6];
    const float* b_p1  = (const float*)d_in[7];
    const float* gg1   = (const float*)d_in[8];
    const float* be1   = (const float*)d_in[9];
    const float* in_w  = (const float*)d_in[10];
    const float* in_b  = (const float*)d_in[11];
    const float* out_w = (const float*)d_in[12];
    const float* out_b = (const float*)d_in[13];
    const float* ew_w1 = (const float*)d_in[14];
    const float* ew_b1 = (const float*)d_in[15];
    const float* ew_w2 = (const float*)d_in[16];
    const float* ew_b2 = (const float*)d_in[17];

    float* H  = (float*)d_out;
    float* ew = H + (size_t)Nn * Nn;

    float *seq, *qkv, *att, *S, *hidden;
    uint16_t *ah, *al, *bh, *bl, *fh, *fl;
    cudaGetSymbolAddress((void**)&seq, g_seq);
    cudaGetSymbolAddress((void**)&qkv, g_qkv);
    cudaGetSymbolAddress((void**)&att, g_att);
    cudaGetSymbolAddress((void**)&S, g_S);
    cudaGetSymbolAddress((void**)&hidden, g_hidden);
    cudaGetSymbolAddress((void**)&ah, g_ah);
    cudaGetSymbolAddress((void**)&al, g_al);
    cudaGetSymbolAddress((void**)&bh, g_bh);
    cudaGetSymbolAddress((void**)&bl, g_bl);
    cudaGetSymbolAddress((void**)&fh, g_fh);
    cudaGetSymbolAddress((void**)&fl, g_fl);

    cudaMemsetAsync(H, 0, (size_t)Nn * Nn * sizeof(float));

    // 1) modality projections: Linear+bias+ReLU, interleaved into seq (fp32)
    do_split(x0, ah, al, (size_t)Nn * Dd);
    do_split(w_p0, bh, bl, (size_t)Dd * Dd);
    tgemm<1, 1><<<dim3(Dd / 128, Nn / 128), 256>>>(ah, al, bh, bl, b_p0, seq, 2 * Dd);
    do_split(x1, ah, al, (size_t)Nn * Dd);
    do_split(w_p1, bh, bl, (size_t)Dd * Dd);
    tgemm<1, 1><<<dim3(Dd / 128, Nn / 128), 256>>>(ah, al, bh, bl, b_p1, seq + Dd, 2 * Dd);

    // 2) LayerNorm -> ah/al (bf16 hi/lo) directly
    ln_kernel<<<2 * Nn, 256>>>(gg0, be0, gg1, be1);

    // 3) qkv projection (A = LN output hi/lo)
    do_split(in_w, bh, bl, (size_t)3 * Dd * Dd);
    tgemm<0, 1><<<dim3(3 * Dd / 128, 2 * Nn / 128), 256>>>(ah, al, bh, bl, in_b, qkv, 3 * Dd);

    // 4) 2-token attention -> ctx hi/lo into ah/al (reuse)
    attn_kernel<<<(Nn * NHEADS * 32) / 256, 256>>>();

    // 5) out-proj
    do_split(out_w, bh, bl, (size_t)Dd * Dd);
    tgemm<0, 1><<<dim3(Dd / 128, 2 * Nn / 128), 256>>>(ah, al, bh, bl, out_b, att, Dd);

    // 6) fuse (mean over 2 tokens) -> fh/fl directly
    mean_kernel<<<(Nn * Dd / 4 + 255) / 256, 256>>>();

    // 7) similarity logits S = fused @ fused^T  (symmetric: upper blocks only)
    tgemm_sym<<<(Nn / 128) * (Nn / 128 + 1) / 2, 256>>>(fh, fl, S);

    // 8) row softmax + top-16 + scatter
    topk_kernel<<<Nn, 256, Nn * sizeof(float)>>>(H);

    // 9) edge-weight MLP
    do_split(ew_w1, bh, bl, (size_t)(Dd / 2) * Dd);
    tgemm<1, 1><<<dim3((Dd / 2) / 128, Nn / 128), 256>>>(fh, fl, bh, bl, ew_b1, hidden, Dd / 2);
    ew_kernel<<<(Nn * 32) / 256, 256>>>(ew_w2, ew_b2, ew);
}

// round 7
// speedup vs baseline: 1.1739x; 1.1739x over previous
#include <cuda_runtime.h>
#include <cuda_bf16.h>
#include <math.h>
#include <stdint.h>

#define Nn 8192
#define Dd 512
#define KDIM 512
#define NHEADS 8
#define HDIM 64
#define TOPK 16

// ---------------- scratch (static device globals; no allocation) -------------
__device__ float g_seq[2 * Nn * Dd];
__device__ float g_qkv[2 * Nn * 3 * Dd];
__device__ float g_att[2 * Nn * Dd];
__device__ float g_S[(size_t)Nn * Nn];
__device__ float g_hidden[Nn * (Dd / 2)];
__device__ uint16_t g_ah[2 * Nn * Dd], g_al[2 * Nn * Dd];   // activations hi/lo
__device__ uint16_t g_bh[3 * Dd * Dd], g_bl[3 * Dd * Dd];   // weights hi/lo
__device__ uint16_t g_fh[Nn * Dd], g_fl[Nn * Dd];           // fused hi/lo

// ============================ PTX helpers ====================================
__device__ __forceinline__ uint32_t smem_u32(const void* p) {
    uint32_t a;
    asm("{ .reg .u64 t; cvta.to.shared.u64 t, %1; cvt.u32.u64 %0, t; }" : "=r"(a) : "l"(p));
    return a;
}
__device__ __forceinline__ void cp16(uint32_t dst, const void* src) {
    asm volatile("cp.async.cg.shared.global [%0], [%1], 16;" :: "r"(dst), "l"(src) : "memory");
}
__device__ __forceinline__ void cp_commit() {
    asm volatile("cp.async.commit_group;" ::: "memory");
}
template <int N> __device__ __forceinline__ void cp_wait() {
    asm volatile("cp.async.wait_group %0;" :: "n"(N) : "memory");
}
__device__ __forceinline__ void ldsm4(uint32_t* r, uint32_t a) {
    asm volatile("ldmatrix.sync.aligned.m8n8.x4.shared.b16 {%0,%1,%2,%3}, [%4];"
                 : "=r"(r[0]), "=r"(r[1]), "=r"(r[2]), "=r"(r[3]) : "r"(a));
}
__device__ __forceinline__ void mma16816(float* c, const uint32_t* a, uint32_t b0, uint32_t b1) {
    asm volatile("mma.sync.aligned.m16n8k16.row.col.f32.bf16.bf16.f32 "
                 "{%0,%1,%2,%3}, {%4,%5,%6,%7}, {%8,%9}, {%0,%1,%2,%3};"
                 : "+f"(c[0]), "+f"(c[1]), "+f"(c[2]), "+f"(c[3])
                 : "r"(a[0]), "r"(a[1]), "r"(a[2]), "r"(a[3]), "r"(b0), "r"(b1));
}

// ======================= warp-MMA NT GEMM (bf16 hi/lo, fp32 acc) =============
// C[M,N] = sum over 3 passes: Ah*Bh^T, Ah*Bl^T, Al*Bh^T.  K == 512 everywhere.
// Tile 128x128, BK=32, double-buffered cp.async (round-5 proven structure).
template <int RELU, int HAS_BIAS>
__global__ __launch_bounds__(256, 2) void tgemm(
    const uint16_t* __restrict__ Ahp, const uint16_t* __restrict__ Alp,
    const uint16_t* __restrict__ Bhp, const uint16_t* __restrict__ Blp,
    const float* __restrict__ bias, float* __restrict__ C, int ldc)
{
    __shared__ uint16_t sA[2][128 * 32];
    __shared__ uint16_t sB[2][128 * 32];

    const int tid = threadIdx.x;
    const int lane = tid & 31, wid = tid >> 5;
    const int wm = wid & 3;
    const int wn = wid >> 2;
    const int bm = blockIdx.y * 128, bn = blockIdx.x * 128;

    const uint32_t sa0 = smem_u32(&sA[0][0]), sa1 = smem_u32(&sA[1][0]);
    const uint32_t sb0 = smem_u32(&sB[0][0]), sb1 = smem_u32(&sB[1][0]);

    const uint16_t* Asrc[3] = { Ahp, Ahp, Alp };
    const uint16_t* Bsrc[3] = { Bhp, Blp, Bhp };
    const int CPP = KDIM / 32;
    const int NCHK = 3 * CPP;

    uint32_t lsw[2]; size_t lsrc[2];
#pragma unroll
    for (int i = 0; i < 2; i++) {
        int s = tid + 256 * i;
        int r = s >> 2, c = s & 3;
        lsw[i] = r * 64 + (((c ^ ((r >> 1) & 3))) << 4);
        lsrc[i] = (size_t)r * KDIM + c * 8;
    }

    uint32_t offA[2][2], offB[2][4];
#pragma unroll
    for (int kk = 0; kk < 2; kk++) {
#pragma unroll
        for (int f = 0; f < 2; f++) {
            int r = wm * 32 + f * 16 + (lane & 15);
            int c = kk * 2 + (lane >> 4);
            offA[kk][f] = r * 64 + (((c ^ ((r >> 1) & 3))) << 4);
        }
#pragma unroll
        for (int g = 0; g < 4; g++) {
            int r = wn * 64 + g * 16 + (lane & 7) + ((lane >> 4) << 3);
            int c = kk * 2 + ((lane >> 3) & 1);
            offB[kk][g] = r * 64 + (((c ^ ((r >> 1) & 3))) << 4);
        }
    }

    float acc[2][8][4];
#pragma unroll
    for (int f = 0; f < 2; f++)
#pragma unroll
        for (int g = 0; g < 8; g++)
#pragma unroll
            for (int j = 0; j < 4; j++) acc[f][g][j] = 0.f;

    auto load_chunk = [&](int c, int buf) {
        const int pass = c / CPP;
        const int k0 = (c % CPP) * 32;
        const uint16_t* A = Asrc[pass];
        const uint16_t* B = Bsrc[pass];
        const uint32_t da = buf ? sa1 : sa0;
        const uint32_t db = buf ? sb1 : sb0;
#pragma unroll
        for (int i = 0; i < 2; i++) {
            cp16(da + lsw[i], A + (size_t)bm * KDIM + k0 + lsrc[i]);
            cp16(db + lsw[i], B + (size_t)bn * KDIM + k0 + lsrc[i]);
        }
        cp_commit();
    };

    load_chunk(0, 0);

    for (int c = 0; c < NCHK; c++) {
        const int b = c & 1;
        if (c + 1 < NCHK) { load_chunk(c + 1, b ^ 1); cp_wait<1>(); }
        else cp_wait<0>();
        __syncthreads();

        const uint32_t da = b ? sa1 : sa0;
        const uint32_t db = b ? sb1 : sb0;
#pragma unroll
        for (int kk = 0; kk < 2; kk++) {
            uint32_t ra[2][4], rb[4][4];
#pragma unroll
            for (int f = 0; f < 2; f++) ldsm4(ra[f], da + offA[kk][f]);
#pragma unroll
            for (int g = 0; g < 4; g++) ldsm4(rb[g], db + offB[kk][g]);
#pragma unroll
            for (int f = 0; f < 2; f++)
#pragma unroll
                for (int g = 0; g < 4; g++) {
                    mma16816(acc[f][2 * g + 0], ra[f], rb[g][0], rb[g][1]);
                    mma16816(acc[f][2 * g + 1], ra[f], rb[g][2], rb[g][3]);
                }
        }
        __syncthreads();
    }

    const int col0 = bn + wn * 64 + (lane & 3) * 2;
#pragma unroll
    for (int f = 0; f < 2; f++) {
        const int row0 = bm + wm * 32 + f * 16 + (lane >> 2);
#pragma unroll
        for (int g = 0; g < 8; g++) {
            const int col = col0 + g * 8;
            float b0 = 0.f, b1 = 0.f;
            if (HAS_BIAS) { b0 = bias[col]; b1 = bias[col + 1]; }
            float2 v0, v1;
            v0.x = acc[f][g][0] + b0; v0.y = acc[f][g][1] + b1;
            v1.x = acc[f][g][2] + b0; v1.y = acc[f][g][3] + b1;
            if (RELU) {
                v0.x = fmaxf(v0.x, 0.f); v0.y = fmaxf(v0.y, 0.f);
                v1.x = fmaxf(v1.x, 0.f); v1.y = fmaxf(v1.y, 0.f);
            }
            *(float2*)(C + (size_t)row0 * ldc + col) = v0;
            *(float2*)(C + (size_t)(row0 + 8) * ldc + col) = v1;
        }
    }
}

// ============== symmetric variant: S = F*F^T, upper-triangle blocks ==========
__global__ __launch_bounds__(256, 2) void tgemm_sym(
    const uint16_t* __restrict__ Fh, const uint16_t* __restrict__ Fl,
    float* __restrict__ C)
{
    __shared__ __align__(16) uint8_t smraw[32768];
    uint16_t* sAbase = (uint16_t*)smraw;
    uint16_t* sBbase = (uint16_t*)(smraw + 16384);
    float* smT = (float*)smraw;

    const int tid = threadIdx.x;
    const int lane = tid & 31, wid = tid >> 5;
    const int wm = wid & 3;
    const int wn = wid >> 2;

    int t = blockIdx.x;
    int bj = (int)((sqrtf(8.f * t + 1.f) - 1.f) * 0.5f);
    while ((bj + 1) * (bj + 2) / 2 <= t) bj++;
    while (bj * (bj + 1) / 2 > t) bj--;
    int bi = t - bj * (bj + 1) / 2;
    const int bm = bi * 128, bn = bj * 128;

    const uint32_t sa0 = smem_u32(sAbase), sa1 = smem_u32(sAbase + 4096);
    const uint32_t sb0 = smem_u32(sBbase), sb1 = smem_u32(sBbase + 4096);

    const uint16_t* Asrc[3] = { Fh, Fh, Fl };
    const uint16_t* Bsrc[3] = { Fh, Fl, Fh };
    const int CPP = KDIM / 32;
    const int NCHK = 3 * CPP;

    uint32_t lsw[2]; size_t lsrc[2];
#pragma unroll
    for (int i = 0; i < 2; i++) {
        int s = tid + 256 * i;
        int r = s >> 2, c = s & 3;
        lsw[i] = r * 64 + (((c ^ ((r >> 1) & 3))) << 4);
        lsrc[i] = (size_t)r * KDIM + c * 8;
    }

    uint32_t offA[2][2], offB[2][4];
#pragma unroll
    for (int kk = 0; kk < 2; kk++) {
#pragma unroll
        for (int f = 0; f < 2; f++) {
            int r = wm * 32 + f * 16 + (lane & 15);
            int c = kk * 2 + (lane >> 4);
            offA[kk][f] = r * 64 + (((c ^ ((r >> 1) & 3))) << 4);
        }
#pragma unroll
        for (int g = 0; g < 4; g++) {
            int r = wn * 64 + g * 16 + (lane & 7) + ((lane >> 4) << 3);
            int c = kk * 2 + ((lane >> 3) & 1);
            offB[kk][g] = r * 64 + (((c ^ ((r >> 1) & 3))) << 4);
        }
    }

    float acc[2][8][4];
#pragma unroll
    for (int f = 0; f < 2; f++)
#pragma unroll
        for (int g = 0; g < 8; g++)
#pragma unroll
            for (int j = 0; j < 4; j++) acc[f][g][j] = 0.f;

    auto load_chunk = [&](int c, int buf) {
        const int pass = c / CPP;
        const int k0 = (c % CPP) * 32;
        const uint16_t* A = Asrc[pass];
        const uint16_t* B = Bsrc[pass];
        const uint32_t da = buf ? sa1 : sa0;
        const uint32_t db = buf ? sb1 : sb0;
#pragma unroll
        for (int i = 0; i < 2; i++) {
            cp16(da + lsw[i], A + (size_t)bm * KDIM + k0 + lsrc[i]);
            cp16(db + lsw[i], B + (size_t)bn * KDIM + k0 + lsrc[i]);
        }
        cp_commit();
    };

    load_chunk(0, 0);

    for (int c = 0; c < NCHK; c++) {
        const int b = c & 1;
        if (c + 1 < NCHK) { load_chunk(c + 1, b ^ 1); cp_wait<1>(); }
        else cp_wait<0>();
        __syncthreads();

        const uint32_t da = b ? sa1 : sa0;
        const uint32_t db = b ? sb1 : sb0;
#pragma unroll
        for (int kk = 0; kk < 2; kk++) {
            uint32_t ra[2][4], rb[4][4];
#pragma unroll
            for (int f = 0; f < 2; f++) ldsm4(ra[f], da + offA[kk][f]);
#pragma unroll
            for (int g = 0; g < 4; g++) ldsm4(rb[g], db + offB[kk][g]);
#pragma unroll
            for (int f = 0; f < 2; f++)
#pragma unroll
                for (int g = 0; g < 4; g++) {
                    mma16816(acc[f][2 * g + 0], ra[f], rb[g][0], rb[g][1]);
                    mma16816(acc[f][2 * g + 1], ra[f], rb[g][2], rb[g][3]);
                }
        }
        __syncthreads();
    }

    const int col0 = bn + wn * 64 + (lane & 3) * 2;
#pragma unroll
    for (int f = 0; f < 2; f++) {
        const int row0 = bm + wm * 32 + f * 16 + (lane >> 2);
#pragma unroll
        for (int g = 0; g < 8; g++) {
            const int col = col0 + g * 8;
            float2 v0, v1;
            v0.x = acc[f][g][0]; v0.y = acc[f][g][1];
            v1.x = acc[f][g][2]; v1.y = acc[f][g][3];
            *(float2*)(C + (size_t)row0 * Nn + col) = v0;
            *(float2*)(C + (size_t)(row0 + 8) * Nn + col) = v1;
        }
    }

    if (bi != bj) {
#pragma unroll
        for (int cc = 0; cc < 2; cc++) {
            __syncthreads();
            float* buf = smT + wn * (32 * 128);
#pragma unroll
            for (int gl = 0; gl < 4; gl++) {
                const int g = cc * 4 + gl;
                const int cl = gl * 8 + (lane & 3) * 2;
#pragma unroll
                for (int f = 0; f < 2; f++) {
                    const int r = wm * 32 + f * 16 + (lane >> 2);
                    buf[cl * 128 + r]           = acc[f][g][0];
                    buf[(cl + 1) * 128 + r]     = acc[f][g][1];
                    buf[cl * 128 + r + 8]       = acc[f][g][2];
                    buf[(cl + 1) * 128 + r + 8] = acc[f][g][3];
                }
            }
            __syncthreads();
            for (int idx = tid; idx < 64 * 32; idx += 256) {
                const int rr = idx >> 5;
                const int sg = idx & 31;
                const int b2 = rr >> 5;
                const int cl = rr & 31;
                const int cAbs = bn + b2 * 64 + cc * 32 + cl;
                float4 v = *(float4*)(smT + b2 * (32 * 128) + cl * 128 + sg * 4);
                *(float4*)(C + (size_t)cAbs * Nn + bm + sg * 4) = v;
            }
        }
    }
}

// ---------------- fp32 -> (hi, lo) bf16 split --------------------------------
__global__ void split_kernel(const float* __restrict__ x, uint16_t* __restrict__ hi,
                             uint16_t* __restrict__ lo, int n4)
{
    int i = blockIdx.x * blockDim.x + threadIdx.x;
    if (i >= n4) return;
    float4 v = ((const float4*)x)[i];
    __nv_bfloat16 h0 = __float2bfloat16(v.x), h1 = __float2bfloat16(v.y);
    __nv_bfloat16 h2 = __float2bfloat16(v.z), h3 = __float2bfloat16(v.w);
    __nv_bfloat16 l0 = __float2bfloat16(v.x - __bfloat162float(h0));
    __nv_bfloat16 l1 = __float2bfloat16(v.y - __bfloat162float(h1));
    __nv_bfloat16 l2 = __float2bfloat16(v.z - __bfloat162float(h2));
    __nv_bfloat16 l3 = __float2bfloat16(v.w - __bfloat162float(h3));
    ushort4 hv, lv;
    hv.x = __bfloat16_as_ushort(h0); hv.y = __bfloat16_as_ushort(h1);
    hv.z = __bfloat16_as_ushort(h2); hv.w = __bfloat16_as_ushort(h3);
    lv.x = __bfloat16_as_ushort(l0); lv.y = __bfloat16_as_ushort(l1);
    lv.z = __bfloat16_as_ushort(l2); lv.w = __bfloat16_as_ushort(l3);
    ((ushort4*)hi)[i] = hv;
    ((ushort4*)lo)[i] = lv;
}

// ---------------- LayerNorm -> bf16 hi/lo directly ---------------------------
__global__ void ln_kernel(const float* __restrict__ g0, const float* __restrict__ be0,
                          const float* __restrict__ g1, const float* __restrict__ be1)
{
    int row = blockIdx.x;
    const float* x = g_seq + (size_t)row * Dd;
    int tid = threadIdx.x;
    float v0 = x[tid], v1 = x[tid + 256];
    __shared__ float rs[256], rq[256];
    rs[tid] = v0 + v1;
    rq[tid] = v0 * v0 + v1 * v1;
    __syncthreads();
    for (int st = 128; st > 0; st >>= 1) {
        if (tid < st) { rs[tid] += rs[tid + st]; rq[tid] += rq[tid + st]; }
        __syncthreads();
    }
    float mean = rs[0] * (1.f / Dd);
    float var = rq[0] * (1.f / Dd) - mean * mean;
    float inv = rsqrtf(var + 1e-5f);
    const float* gg = (row & 1) ? g1 : g0;
    const float* bb = (row & 1) ? be1 : be0;
    float y0 = (v0 - mean) * inv * gg[tid] + bb[tid];
    float y1 = (v1 - mean) * inv * gg[tid + 256] + bb[tid + 256];
    size_t base = (size_t)row * Dd;
    __nv_bfloat16 h0 = __float2bfloat16(y0), h1 = __float2bfloat16(y1);
    g_ah[base + tid]       = __bfloat16_as_ushort(h0);
    g_ah[base + tid + 256] = __bfloat16_as_ushort(h1);
    g_al[base + tid]       = __bfloat16_as_ushort(__float2bfloat16(y0 - __bfloat162float(h0)));
    g_al[base + tid + 256] = __bfloat16_as_ushort(__float2bfloat16(y1 - __bfloat162float(h1)));
}

// ---------------- 2-token multihead attention -> ctx hi/lo -------------------
__global__ void attn_kernel()
{
    int gt = blockIdx.x * blockDim.x + threadIdx.x;
    int gw = gt >> 5, lane = gt & 31;
    if (gw >= Nn * NHEADS) return;
    int node = gw >> 3, h = gw & 7;
    const float* base = g_qkv + (size_t)node * 2 * (3 * Dd);
    int d0 = lane * 2;
    float q[2][2], k[2][2], v[2][2];
#pragma unroll
    for (int t = 0; t < 2; t++) {
        const float* r = base + t * (3 * Dd) + h * HDIM;
        float2 qq = *(const float2*)(r + d0);
        float2 kk = *(const float2*)(r + Dd + d0);
        float2 vv = *(const float2*)(r + 2 * Dd + d0);
        q[t][0] = qq.x; q[t][1] = qq.y;
        k[t][0] = kk.x; k[t][1] = kk.y;
        v[t][0] = vv.x; v[t][1] = vv.y;
    }
    float s[2][2];
#pragma unroll
    for (int qi = 0; qi < 2; qi++)
#pragma unroll
        for (int ki = 0; ki < 2; ki++)
            s[qi][ki] = q[qi][0] * k[ki][0] + q[qi][1] * k[ki][1];
#pragma unroll
    for (int o = 16; o > 0; o >>= 1)
#pragma unroll
        for (int qi = 0; qi < 2; qi++)
#pragma unroll
            for (int ki = 0; ki < 2; ki++)
                s[qi][ki] += __shfl_xor_sync(0xffffffffu, s[qi][ki], o);
    const float scale = 0.125f;
#pragma unroll
    for (int qi = 0; qi < 2; qi++) {
        float a0 = s[qi][0] * scale, a1 = s[qi][1] * scale;
        float m = fmaxf(a0, a1);
        float e0 = expf(a0 - m), e1 = expf(a1 - m);
        float inv = 1.f / (e0 + e1);
        float w0 = e0 * inv, w1 = e1 * inv;
        float o0 = w0 * v[0][0] + w1 * v[1][0];
        float o1 = w0 * v[0][1] + w1 * v[1][1];
        size_t off = (size_t)(node * 2 + qi) * Dd + h * HDIM + d0;
        __nv_bfloat16 h0 = __float2bfloat16(o0), h1 = __float2bfloat16(o1);
        ushort2 hv, lv;
        hv.x = __bfloat16_as_ushort(h0); hv.y = __bfloat16_as_ushort(h1);
        lv.x = __bfloat16_as_ushort(__float2bfloat16(o0 - __bfloat162float(h0)));
        lv.y = __bfloat16_as_ushort(__float2bfloat16(o1 - __bfloat162float(h1)));
        *(ushort2*)(g_ah + off) = hv;
        *(ushort2*)(g_al + off) = lv;
    }
}

// ---------------- mean over the 2 tokens -> fused hi/lo ----------------------
__global__ void mean_kernel()
{
    int i = blockIdx.x * blockDim.x + threadIdx.x;
    if (i >= Nn * Dd / 4) return;
    int e0 = i * 4;
    int node = e0 / Dd, d = e0 - node * Dd;
    const float* r0 = g_att + (size_t)(node * 2) * Dd + d;
    const float* r1 = g_att + (size_t)(node * 2 + 1) * Dd + d;
    float4 a = *(const float4*)r0, b = *(const float4*)r1;
    float f0 = 0.5f * (a.x + b.x), f1 = 0.5f * (a.y + b.y);
    float f2 = 0.5f * (a.z + b.z), f3 = 0.5f * (a.w + b.w);
    __nv_bfloat16 h0 = __float2bfloat16(f0), h1 = __float2bfloat16(f1);
    __nv_bfloat16 h2 = __float2bfloat16(f2), h3 = __float2bfloat16(f3);
    ushort4 hv, lv;
    hv.x = __bfloat16_as_ushort(h0); hv.y = __bfloat16_as_ushort(h1);
    hv.z = __bfloat16_as_ushort(h2); hv.w = __bfloat16_as_ushort(h3);
    lv.x = __bfloat16_as_ushort(__float2bfloat16(f0 - __bfloat162float(h0)));
    lv.y = __bfloat16_as_ushort(__float2bfloat16(f1 - __bfloat162float(h1)));
    lv.z = __bfloat16_as_ushort(__float2bfloat16(f2 - __bfloat162float(h2)));
    lv.w = __bfloat16_as_ushort(__float2bfloat16(f3 - __bfloat162float(h3)));
    ((ushort4*)g_fh)[i] = hv;
    ((ushort4*)g_fl)[i] = lv;
}

// ---------------- softmax stats + top-16 via segment-max hierarchy ----------
// sh[0..Nn) = row copy; segmax[s] = max of segment s (32 elems). Extraction:
// argmax over 256 segment maxima, then rescan only the winning segment.
__global__ void topk_kernel(float* __restrict__ Hout)
{
    int row = blockIdx.x;
    extern __shared__ float sh[];                 // Nn floats + 256 segmax
    float* segmax = sh + Nn;
    __shared__ float swv[8];
    __shared__ int swi[8];
    __shared__ float s_bcast;
    __shared__ int s_seg;
    __shared__ float topv[TOPK];
    __shared__ int topi[TOPK];
    const float* srow = g_S + (size_t)row * Nn;
    int tid = threadIdx.x;
    int lane = tid & 31, wid = tid >> 5;

    // load row into smem (coalesced)
    for (int j = tid; j < Nn; j += 256) sh[j] = srow[j];
    __syncthreads();

    // per-thread segment max (rotated index -> conflict-free)
    {
        const int base = tid * 32;
        float sm = -INFINITY;
#pragma unroll 8
        for (int i = 0; i < 32; i++)
            sm = fmaxf(sm, sh[base + ((i + tid) & 31)]);
        segmax[tid] = sm;
        // row max = block max of sm
        float lmax = sm;
#pragma unroll
        for (int o = 16; o > 0; o >>= 1)
            lmax = fmaxf(lmax, __shfl_xor_sync(0xffffffffu, lmax, o));
        if (lane == 0) swv[wid] = lmax;
    }
    __syncthreads();
    if (tid == 0) {
        float m = swv[0];
#pragma unroll
        for (int w = 1; w < 8; w++) m = fmaxf(m, swv[w]);
        s_bcast = m;
    }
    __syncthreads();
    const float rmax = s_bcast;

    // sum of exp
    float lsum = 0.f;
    for (int j = tid; j < Nn; j += 256) lsum += expf(sh[j] - rmax);
#pragma unroll
    for (int o = 16; o > 0; o >>= 1)
        lsum += __shfl_xor_sync(0xffffffffu, lsum, o);
    if (lane == 0) swv[wid] = lsum;
    __syncthreads();
    if (tid == 0) {
        float s = 0.f;
#pragma unroll
        for (int w = 0; w < 8; w++) s += swv[w];
        s_bcast = 1.f / s;
    }
    __syncthreads();
    const float rinv = s_bcast;

    // 16 extraction rounds
    for (int kk = 0; kk < TOPK; kk++) {
        // block argmax over segmax[256] (value desc, index asc on ties)
        float v = segmax[tid];
        int idx = tid;
#pragma unroll
        for (int o = 16; o > 0; o >>= 1) {
            float ov = __shfl_xor_sync(0xffffffffu, v, o);
            int oi = __shfl_xor_sync(0xffffffffu, idx, o);
            if (ov > v || (ov == v && oi < idx)) { v = ov; idx = oi; }
        }
        if (lane == 0) { swv[wid] = v; swi[wid] = idx; }
        __syncthreads();
        if (tid == 0) {
            float bv = swv[0]; int bi = swi[0];
#pragma unroll
            for (int w = 1; w < 8; w++)
                if (swv[w] > bv || (swv[w] == bv && swi[w] < bi)) { bv = swv[w]; bi = swi[w]; }
            s_seg = bi;
        }
        __syncthreads();
        const int s = s_seg;
        // warp 0: find max element inside segment s, remove it, refresh segmax
        if (wid == 0) {
            int ei = s * 32 + lane;
            float ev = sh[ei];
            float v2 = ev; int i2 = ei;
#pragma unroll
            for (int o = 16; o > 0; o >>= 1) {
                float ov = __shfl_xor_sync(0xffffffffu, v2, o);
                int oi = __shfl_xor_sync(0xffffffffu, i2, o);
                if (ov > v2 || (ov == v2 && oi < i2)) { v2 = ov; i2 = oi; }
            }
            // all lanes now hold winner (v2, i2)
            if (lane == 0) { topv[kk] = v2; topi[kk] = i2; }
            float nv = (ei == i2) ? -INFINITY : ev;
            if (ei == i2) sh[ei] = -INFINITY;
            float mx = nv;
#pragma unroll
            for (int o = 16; o > 0; o >>= 1)
                mx = fmaxf(mx, __shfl_xor_sync(0xffffffffu, mx, o));
            if (lane == 0) segmax[s] = mx;
        }
        __syncthreads();
    }

    if (tid == 0) {
        Hout[(size_t)row * Nn + row] = 1.0f;
#pragma unroll
        for (int kk = 0; kk < TOPK; kk++)
            Hout[(size_t)topi[kk] * Nn + row] = expf(topv[kk] - rmax) * rinv;
    }
}

__global__ void ew_kernel(const float* __restrict__ w2, const float* __restrict__ b2,
                          float* __restrict__ out)
{
    int gt = blockIdx.x * blockDim.x + threadIdx.x;
    int gw = gt >> 5, lane = gt & 31;
    if (gw >= Nn) return;
    const float* hrow = g_hidden + (size_t)gw * (Dd / 2);
    float s = 0.f;
    for (int j = lane; j < Dd / 2; j += 32) s += hrow[j] * w2[j];
#pragma unroll
    for (int o = 16; o > 0; o >>= 1) s += __shfl_xor_sync(0xffffffffu, s, o);
    if (lane == 0) {
        float v = s + b2[0];
        float sig = 1.f / (1.f + expf(-v));
        out[gw] = fmaxf(sig, 1e-8f);
    }
}

// ---------------- launch ------------------------------------------------------
static void do_split(const float* src, uint16_t* hi, uint16_t* lo, size_t n)
{
    int n4 = (int)(n / 4);
    split_kernel<<<(n4 + 255) / 256, 256>>>(src, hi, lo, n4);
}

extern "C" void kernel_launch(void* const* d_in, const int* in_sizes, int n_in,
                              void* d_out, int out_size)
{
    const float* x0    = (const float*)d_in[0];
    const float* x1    = (const float*)d_in[1];
    const float* w_p0  = (const float*)d_in[2];
    const float* b_p0  = (const float*)d_in[3];
    const float* gg0   = (const float*)d_in[4];
    const float* be0   = (const float*)d_in[5];
    const float* w_p1  = (const float*)d_in[6];
    const float* b_p1  = (const float*)d_in[7];
    const float* gg1   = (const float*)d_in[8];
    const float* be1   = (const float*)d_in[9];
    const float* in_w  = (const float*)d_in[10];
    const float* in_b  = (const float*)d_in[11];
    const float* out_w = (const float*)d_in[12];
    const float* out_b = (const float*)d_in[13];
    const float* ew_w1 = (const float*)d_in[14];
    const float* ew_b1 = (const float*)d_in[15];
    const float* ew_w2 = (const float*)d_in[16];
    const float* ew_b2 = (const float*)d_in[17];

    float* H  = (float*)d_out;
    float* ew = H + (size_t)Nn * Nn;

    float *seq, *qkv, *att, *S, *hidden;
    uint16_t *ah, *al, *bh, *bl, *fh, *fl;
    cudaGetSymbolAddress((void**)&seq, g_seq);
    cudaGetSymbolAddress((void**)&qkv, g_qkv);
    cudaGetSymbolAddress((void**)&att, g_att);
    cudaGetSymbolAddress((void**)&S, g_S);
    cudaGetSymbolAddress((void**)&hidden, g_hidden);
    cudaGetSymbolAddress((void**)&ah, g_ah);
    cudaGetSymbolAddress((void**)&al, g_al);
    cudaGetSymbolAddress((void**)&bh, g_bh);
    cudaGetSymbolAddress((void**)&bl, g_bl);
    cudaGetSymbolAddress((void**)&fh, g_fh);
    cudaGetSymbolAddress((void**)&fl, g_fl);

    cudaMemsetAsync(H, 0, (size_t)Nn * Nn * sizeof(float));

    // 1) modality projections: Linear+bias+ReLU, interleaved into seq (fp32)
    do_split(x0, ah, al, (size_t)Nn * Dd);
    do_split(w_p0, bh, bl, (size_t)Dd * Dd);
    tgemm<1, 1><<<dim3(Dd / 128, Nn / 128), 256>>>(ah, al, bh, bl, b_p0, seq, 2 * Dd);
    do_split(x1, ah, al, (size_t)Nn * Dd);
    do_split(w_p1, bh, bl, (size_t)Dd * Dd);
    tgemm<1, 1><<<dim3(Dd / 128, Nn / 128), 256>>>(ah, al, bh, bl, b_p1, seq + Dd, 2 * Dd);

    // 2) LayerNorm -> ah/al (bf16 hi/lo) directly
    ln_kernel<<<2 * Nn, 256>>>(gg0, be0, gg1, be1);

    // 3) qkv projection (A = LN output hi/lo)
    do_split(in_w, bh, bl, (size_t)3 * Dd * Dd);
    tgemm<0, 1><<<dim3(3 * Dd / 128, 2 * Nn / 128), 256>>>(ah, al, bh, bl, in_b, qkv, 3 * Dd);

    // 4) 2-token attention -> ctx hi/lo into ah/al (reuse)
    attn_kernel<<<(Nn * NHEADS * 32) / 256, 256>>>();

    // 5) out-proj
    do_split(out_w, bh, bl, (size_t)Dd * Dd);
    tgemm<0, 1><<<dim3(Dd / 128, 2 * Nn / 128), 256>>>(ah, al, bh, bl, out_b, att, Dd);

    // 6) fuse (mean over 2 tokens) -> fh/fl directly
    mean_kernel<<<(Nn * Dd / 4 + 255) / 256, 256>>>();

    // 7) similarity logits S = fused @ fused^T  (symmetric: upper blocks only)
    tgemm_sym<<<(Nn / 128) * (Nn / 128 + 1) / 2, 256>>>(fh, fl, S);

    // 8) row softmax + top-16 + scatter (segment-max hierarchy)
    topk_kernel<<<Nn, 256, (Nn + 256) * sizeof(float)>>>(H);

    // 9) edge-weight MLP
    do_split(ew_w1, bh, bl, (size_t)(Dd / 2) * Dd);
    tgemm<1, 1><<<dim3((Dd / 2) / 128, Nn / 128), 256>>>(fh, fl, bh, bl, ew_b1, hidden, Dd / 2);
    ew_kernel<<<(Nn * 32) / 256, 256>>>(ew_w2, ew_b2, ew);
}

// round 8
// speedup vs baseline: 1.2233x; 1.0420x over previous
#include <cuda_runtime.h>
#include <cuda_bf16.h>
#include <math.h>
#include <stdint.h>

#define Nn 8192
#define Dd 512
#define KDIM 512
#define NHEADS 8
#define HDIM 64
#define TOPK 16

// ---------------- scratch (static device globals; no allocation) -------------
__device__ float g_seq[2 * Nn * Dd];
__device__ float g_qkv[2 * Nn * 3 * Dd];
__device__ float g_att[2 * Nn * Dd];
__device__ float g_S[(size_t)Nn * Nn];
__device__ float g_hidden[Nn * (Dd / 2)];
__device__ uint16_t g_ah[2 * Nn * Dd], g_al[2 * Nn * Dd];   // activations hi/lo
__device__ uint16_t g_bh[3 * Dd * Dd], g_bl[3 * Dd * Dd];   // weights hi/lo
__device__ uint16_t g_fh[Nn * Dd], g_fl[Nn * Dd];           // fused hi/lo

// ============================ PTX helpers ====================================
__device__ __forceinline__ uint32_t smem_u32(const void* p) {
    uint32_t a;
    asm("{ .reg .u64 t; cvta.to.shared.u64 t, %1; cvt.u32.u64 %0, t; }" : "=r"(a) : "l"(p));
    return a;
}
__device__ __forceinline__ void cp16(uint32_t dst, const void* src) {
    asm volatile("cp.async.cg.shared.global [%0], [%1], 16;" :: "r"(dst), "l"(src) : "memory");
}
__device__ __forceinline__ void cp_commit() {
    asm volatile("cp.async.commit_group;" ::: "memory");
}
template <int N> __device__ __forceinline__ void cp_wait() {
    asm volatile("cp.async.wait_group %0;" :: "n"(N) : "memory");
}
__device__ __forceinline__ void ldsm4(uint32_t* r, uint32_t a) {
    asm volatile("ldmatrix.sync.aligned.m8n8.x4.shared.b16 {%0,%1,%2,%3}, [%4];"
                 : "=r"(r[0]), "=r"(r[1]), "=r"(r[2]), "=r"(r[3]) : "r"(a));
}
__device__ __forceinline__ void mma16816(float* c, const uint32_t* a, uint32_t b0, uint32_t b1) {
    asm volatile("mma.sync.aligned.m16n8k16.row.col.f32.bf16.bf16.f32 "
                 "{%0,%1,%2,%3}, {%4,%5,%6,%7}, {%8,%9}, {%0,%1,%2,%3};"
                 : "+f"(c[0]), "+f"(c[1]), "+f"(c[2]), "+f"(c[3])
                 : "r"(a[0]), "r"(a[1]), "r"(a[2]), "r"(a[3]), "r"(b0), "r"(b1));
}

// ======================= warp-MMA NT GEMM (bf16 hi/lo, fp32 acc) =============
// C[M,N] = sum over 3 passes: Ah*Bh^T, Ah*Bl^T, Al*Bh^T.  K == 512 everywhere.
// Tile 128x128, BK=32, double-buffered cp.async.
// 4 warps (128 thr), 2x2 warp grid, 64x64 warp tiles: smem reread 2x+2x.
template <int RELU, int HAS_BIAS>
__global__ __launch_bounds__(128, 2) void tgemm(
    const uint16_t* __restrict__ Ahp, const uint16_t* __restrict__ Alp,
    const uint16_t* __restrict__ Bhp, const uint16_t* __restrict__ Blp,
    const float* __restrict__ bias, float* __restrict__ C, int ldc)
{
    __shared__ uint16_t sA[2][128 * 32];
    __shared__ uint16_t sB[2][128 * 32];

    const int tid = threadIdx.x;
    const int lane = tid & 31, wid = tid >> 5;
    const int wm = wid & 1;          // 2 warps over M (64 rows each)
    const int wn = wid >> 1;         // 2 warps over N (64 cols each)
    const int bm = blockIdx.y * 128, bn = blockIdx.x * 128;

    const uint32_t sa0 = smem_u32(&sA[0][0]), sa1 = smem_u32(&sA[1][0]);
    const uint32_t sb0 = smem_u32(&sB[0][0]), sb1 = smem_u32(&sB[1][0]);

    const uint16_t* Asrc[3] = { Ahp, Ahp, Alp };
    const uint16_t* Bsrc[3] = { Bhp, Blp, Bhp };
    const int CPP = KDIM / 32;
    const int NCHK = 3 * CPP;

    uint32_t lsw[4]; size_t lsrc[4];
#pragma unroll
    for (int i = 0; i < 4; i++) {
        int s = tid + 128 * i;               // 0..511 segments
        int r = s >> 2, c = s & 3;
        lsw[i] = r * 64 + (((c ^ ((r >> 1) & 3))) << 4);
        lsrc[i] = (size_t)r * KDIM + c * 8;
    }

    uint32_t offA[2][4], offB[2][4];
#pragma unroll
    for (int kk = 0; kk < 2; kk++) {
#pragma unroll
        for (int f = 0; f < 4; f++) {
            int r = wm * 64 + f * 16 + (lane & 15);
            int c = kk * 2 + (lane >> 4);
            offA[kk][f] = r * 64 + (((c ^ ((r >> 1) & 3))) << 4);
        }
#pragma unroll
        for (int g = 0; g < 4; g++) {
            int r = wn * 64 + g * 16 + (lane & 7) + ((lane >> 4) << 3);
            int c = kk * 2 + ((lane >> 3) & 1);
            offB[kk][g] = r * 64 + (((c ^ ((r >> 1) & 3))) << 4);
        }
    }

    float acc[4][8][4];
#pragma unroll
    for (int f = 0; f < 4; f++)
#pragma unroll
        for (int g = 0; g < 8; g++)
#pragma unroll
            for (int j = 0; j < 4; j++) acc[f][g][j] = 0.f;

    auto load_chunk = [&](int c, int buf) {
        const int pass = c / CPP;
        const int k0 = (c % CPP) * 32;
        const uint16_t* A = Asrc[pass];
        const uint16_t* B = Bsrc[pass];
        const uint32_t da = buf ? sa1 : sa0;
        const uint32_t db = buf ? sb1 : sb0;
#pragma unroll
        for (int i = 0; i < 4; i++) {
            cp16(da + lsw[i], A + (size_t)bm * KDIM + k0 + lsrc[i]);
            cp16(db + lsw[i], B + (size_t)bn * KDIM + k0 + lsrc[i]);
        }
        cp_commit();
    };

    load_chunk(0, 0);

    for (int c = 0; c < NCHK; c++) {
        const int b = c & 1;
        if (c + 1 < NCHK) { load_chunk(c + 1, b ^ 1); cp_wait<1>(); }
        else cp_wait<0>();
        __syncthreads();

        const uint32_t da = b ? sa1 : sa0;
        const uint32_t db = b ? sb1 : sb0;
#pragma unroll
        for (int kk = 0; kk < 2; kk++) {
            uint32_t ra[4][4], rb[4][4];
#pragma unroll
            for (int f = 0; f < 4; f++) ldsm4(ra[f], da + offA[kk][f]);
#pragma unroll
            for (int g = 0; g < 4; g++) ldsm4(rb[g], db + offB[kk][g]);
#pragma unroll
            for (int f = 0; f < 4; f++)
#pragma unroll
                for (int g = 0; g < 4; g++) {
                    mma16816(acc[f][2 * g + 0], ra[f], rb[g][0], rb[g][1]);
                    mma16816(acc[f][2 * g + 1], ra[f], rb[g][2], rb[g][3]);
                }
        }
        __syncthreads();
    }

    const int col0 = bn + wn * 64 + (lane & 3) * 2;
#pragma unroll
    for (int f = 0; f < 4; f++) {
        const int row0 = bm + wm * 64 + f * 16 + (lane >> 2);
#pragma unroll
        for (int g = 0; g < 8; g++) {
            const int col = col0 + g * 8;
            float b0 = 0.f, b1 = 0.f;
            if (HAS_BIAS) { b0 = bias[col]; b1 = bias[col + 1]; }
            float2 v0, v1;
            v0.x = acc[f][g][0] + b0; v0.y = acc[f][g][1] + b1;
            v1.x = acc[f][g][2] + b0; v1.y = acc[f][g][3] + b1;
            if (RELU) {
                v0.x = fmaxf(v0.x, 0.f); v0.y = fmaxf(v0.y, 0.f);
                v1.x = fmaxf(v1.x, 0.f); v1.y = fmaxf(v1.y, 0.f);
            }
            *(float2*)(C + (size_t)row0 * ldc + col) = v0;
            *(float2*)(C + (size_t)(row0 + 8) * ldc + col) = v1;
        }
    }
}

// ============== symmetric variant: S = F*F^T, upper-triangle blocks ==========
__global__ __launch_bounds__(128, 2) void tgemm_sym(
    const uint16_t* __restrict__ Fh, const uint16_t* __restrict__ Fl,
    float* __restrict__ C)
{
    __shared__ __align__(16) uint8_t smraw[32768];
    uint16_t* sAbase = (uint16_t*)smraw;
    uint16_t* sBbase = (uint16_t*)(smraw + 16384);
    float* smT = (float*)smraw;

    const int tid = threadIdx.x;
    const int lane = tid & 31, wid = tid >> 5;
    const int wm = wid & 1;
    const int wn = wid >> 1;

    int t = blockIdx.x;
    int bj = (int)((sqrtf(8.f * t + 1.f) - 1.f) * 0.5f);
    while ((bj + 1) * (bj + 2) / 2 <= t) bj++;
    while (bj * (bj + 1) / 2 > t) bj--;
    int bi = t - bj * (bj + 1) / 2;
    const int bm = bi * 128, bn = bj * 128;

    const uint32_t sa0 = smem_u32(sAbase), sa1 = smem_u32(sAbase + 4096);
    const uint32_t sb0 = smem_u32(sBbase), sb1 = smem_u32(sBbase + 4096);

    const uint16_t* Asrc[3] = { Fh, Fh, Fl };
    const uint16_t* Bsrc[3] = { Fh, Fl, Fh };
    const int CPP = KDIM / 32;
    const int NCHK = 3 * CPP;

    uint32_t lsw[4]; size_t lsrc[4];
#pragma unroll
    for (int i = 0; i < 4; i++) {
        int s = tid + 128 * i;
        int r = s >> 2, c = s & 3;
        lsw[i] = r * 64 + (((c ^ ((r >> 1) & 3))) << 4);
        lsrc[i] = (size_t)r * KDIM + c * 8;
    }

    uint32_t offA[2][4], offB[2][4];
#pragma unroll
    for (int kk = 0; kk < 2; kk++) {
#pragma unroll
        for (int f = 0; f < 4; f++) {
            int r = wm * 64 + f * 16 + (lane & 15);
            int c = kk * 2 + (lane >> 4);
            offA[kk][f] = r * 64 + (((c ^ ((r >> 1) & 3))) << 4);
        }
#pragma unroll
        for (int g = 0; g < 4; g++) {
            int r = wn * 64 + g * 16 + (lane & 7) + ((lane >> 4) << 3);
            int c = kk * 2 + ((lane >> 3) & 1);
            offB[kk][g] = r * 64 + (((c ^ ((r >> 1) & 3))) << 4);
        }
    }

    float acc[4][8][4];
#pragma unroll
    for (int f = 0; f < 4; f++)
#pragma unroll
        for (int g = 0; g < 8; g++)
#pragma unroll
            for (int j = 0; j < 4; j++) acc[f][g][j] = 0.f;

    auto load_chunk = [&](int c, int buf) {
        const int pass = c / CPP;
        const int k0 = (c % CPP) * 32;
        const uint16_t* A = Asrc[pass];
        const uint16_t* B = Bsrc[pass];
        const uint32_t da = buf ? sa1 : sa0;
        const uint32_t db = buf ? sb1 : sb0;
#pragma unroll
        for (int i = 0; i < 4; i++) {
            cp16(da + lsw[i], A + (size_t)bm * KDIM + k0 + lsrc[i]);
            cp16(db + lsw[i], B + (size_t)bn * KDIM + k0 + lsrc[i]);
        }
        cp_commit();
    };

    load_chunk(0, 0);

    for (int c = 0; c < NCHK; c++) {
        const int b = c & 1;
        if (c + 1 < NCHK) { load_chunk(c + 1, b ^ 1); cp_wait<1>(); }
        else cp_wait<0>();
        __syncthreads();

        const uint32_t da = b ? sa1 : sa0;
        const uint32_t db = b ? sb1 : sb0;
#pragma unroll
        for (int kk = 0; kk < 2; kk++) {
            uint32_t ra[4][4], rb[4][4];
#pragma unroll
            for (int f = 0; f < 4; f++) ldsm4(ra[f], da + offA[kk][f]);
#pragma unroll
            for (int g = 0; g < 4; g++) ldsm4(rb[g], db + offB[kk][g]);
#pragma unroll
            for (int f = 0; f < 4; f++)
#pragma unroll
                for (int g = 0; g < 4; g++) {
                    mma16816(acc[f][2 * g + 0], ra[f], rb[g][0], rb[g][1]);
                    mma16816(acc[f][2 * g + 1], ra[f], rb[g][2], rb[g][3]);
                }
        }
        __syncthreads();
    }

    // normal (upper) tile write
    const int col0 = bn + wn * 64 + (lane & 3) * 2;
#pragma unroll
    for (int f = 0; f < 4; f++) {
        const int row0 = bm + wm * 64 + f * 16 + (lane >> 2);
#pragma unroll
        for (int g = 0; g < 8; g++) {
            const int col = col0 + g * 8;
            float2 v0, v1;
            v0.x = acc[f][g][0]; v0.y = acc[f][g][1];
            v1.x = acc[f][g][2]; v1.y = acc[f][g][3];
            *(float2*)(C + (size_t)row0 * Nn + col) = v0;
            *(float2*)(C + (size_t)(row0 + 8) * Nn + col) = v1;
        }
    }

    // mirrored (lower) tile write via smem transpose, coalesced
    if (bi != bj) {
#pragma unroll
        for (int cc = 0; cc < 2; cc++) {
            __syncthreads();
            float* buf = smT + wn * (32 * 128);
#pragma unroll
            for (int gl = 0; gl < 4; gl++) {
                const int g = cc * 4 + gl;
                const int cl = gl * 8 + (lane & 3) * 2;   // local col 0..31
#pragma unroll
                for (int f = 0; f < 4; f++) {
                    const int r = wm * 64 + f * 16 + (lane >> 2);
                    buf[cl * 128 + r]           = acc[f][g][0];
                    buf[(cl + 1) * 128 + r]     = acc[f][g][1];
                    buf[cl * 128 + r + 8]       = acc[f][g][2];
                    buf[(cl + 1) * 128 + r + 8] = acc[f][g][3];
                }
            }
            __syncthreads();
            for (int idx = tid; idx < 64 * 32; idx += 128) {
                const int rr = idx >> 5;
                const int sg = idx & 31;
                const int b2 = rr >> 5;
                const int cl = rr & 31;
                const int cAbs = bn + b2 * 64 + cc * 32 + cl;
                float4 v = *(float4*)(smT + b2 * (32 * 128) + cl * 128 + sg * 4);
                *(float4*)(C + (size_t)cAbs * Nn + bm + sg * 4) = v;
            }
        }
    }
}

// ---------------- fp32 -> (hi, lo) bf16 split --------------------------------
__global__ void split_kernel(const float* __restrict__ x, uint16_t* __restrict__ hi,
                             uint16_t* __restrict__ lo, int n4)
{
    int i = blockIdx.x * blockDim.x + threadIdx.x;
    if (i >= n4) return;
    float4 v = ((const float4*)x)[i];
    __nv_bfloat16 h0 = __float2bfloat16(v.x), h1 = __float2bfloat16(v.y);
    __nv_bfloat16 h2 = __float2bfloat16(v.z), h3 = __float2bfloat16(v.w);
    __nv_bfloat16 l0 = __float2bfloat16(v.x - __bfloat162float(h0));
    __nv_bfloat16 l1 = __float2bfloat16(v.y - __bfloat162float(h1));
    __nv_bfloat16 l2 = __float2bfloat16(v.z - __bfloat162float(h2));
    __nv_bfloat16 l3 = __float2bfloat16(v.w - __bfloat162float(h3));
    ushort4 hv, lv;
    hv.x = __bfloat16_as_ushort(h0); hv.y = __bfloat16_as_ushort(h1);
    hv.z = __bfloat16_as_ushort(h2); hv.w = __bfloat16_as_ushort(h3);
    lv.x = __bfloat16_as_ushort(l0); lv.y = __bfloat16_as_ushort(l1);
    lv.z = __bfloat16_as_ushort(l2); lv.w = __bfloat16_as_ushort(l3);
    ((ushort4*)hi)[i] = hv;
    ((ushort4*)lo)[i] = lv;
}

// ---------------- LayerNorm -> bf16 hi/lo directly ---------------------------
__global__ void ln_kernel(const float* __restrict__ g0, const float* __restrict__ be0,
                          const float* __restrict__ g1, const float* __restrict__ be1)
{
    int row = blockIdx.x;
    const float* x = g_seq + (size_t)row * Dd;
    int tid = threadIdx.x;
    float v0 = x[tid], v1 = x[tid + 256];
    __shared__ float rs[256], rq[256];
    rs[tid] = v0 + v1;
    rq[tid] = v0 * v0 + v1 * v1;
    __syncthreads();
    for (int st = 128; st > 0; st >>= 1) {
        if (tid < st) { rs[tid] += rs[tid + st]; rq[tid] += rq[tid + st]; }
        __syncthreads();
    }
    float mean = rs[0] * (1.f / Dd);
    float var = rq[0] * (1.f / Dd) - mean * mean;
    float inv = rsqrtf(var + 1e-5f);
    const float* gg = (row & 1) ? g1 : g0;
    const float* bb = (row & 1) ? be1 : be0;
    float y0 = (v0 - mean) * inv * gg[tid] + bb[tid];
    float y1 = (v1 - mean) * inv * gg[tid + 256] + bb[tid + 256];
    size_t base = (size_t)row * Dd;
    __nv_bfloat16 h0 = __float2bfloat16(y0), h1 = __float2bfloat16(y1);
    g_ah[base + tid]       = __bfloat16_as_ushort(h0);
    g_ah[base + tid + 256] = __bfloat16_as_ushort(h1);
    g_al[base + tid]       = __bfloat16_as_ushort(__float2bfloat16(y0 - __bfloat162float(h0)));
    g_al[base + tid + 256] = __bfloat16_as_ushort(__float2bfloat16(y1 - __bfloat162float(h1)));
}

// ---------------- 2-token multihead attention -> ctx hi/lo -------------------
__global__ void attn_kernel()
{
    int gt = blockIdx.x * blockDim.x + threadIdx.x;
    int gw = gt >> 5, lane = gt & 31;
    if (gw >= Nn * NHEADS) return;
    int node = gw >> 3, h = gw & 7;
    const float* base = g_qkv + (size_t)node * 2 * (3 * Dd);
    int d0 = lane * 2;
    float q[2][2], k[2][2], v[2][2];
#pragma unroll
    for (int t = 0; t < 2; t++) {
        const float* r = base + t * (3 * Dd) + h * HDIM;
        float2 qq = *(const float2*)(r + d0);
        float2 kk = *(const float2*)(r + Dd + d0);
        float2 vv = *(const float2*)(r + 2 * Dd + d0);
        q[t][0] = qq.x; q[t][1] = qq.y;
        k[t][0] = kk.x; k[t][1] = kk.y;
        v[t][0] = vv.x; v[t][1] = vv.y;
    }
    float s[2][2];
#pragma unroll
    for (int qi = 0; qi < 2; qi++)
#pragma unroll
        for (int ki = 0; ki < 2; ki++)
            s[qi][ki] = q[qi][0] * k[ki][0] + q[qi][1] * k[ki][1];
#pragma unroll
    for (int o = 16; o > 0; o >>= 1)
#pragma unroll
        for (int qi = 0; qi < 2; qi++)
#pragma unroll
            for (int ki = 0; ki < 2; ki++)
                s[qi][ki] += __shfl_xor_sync(0xffffffffu, s[qi][ki], o);
    const float scale = 0.125f;
#pragma unroll
    for (int qi = 0; qi < 2; qi++) {
        float a0 = s[qi][0] * scale, a1 = s[qi][1] * scale;
        float m = fmaxf(a0, a1);
        float e0 = expf(a0 - m), e1 = expf(a1 - m);
        float inv = 1.f / (e0 + e1);
        float w0 = e0 * inv, w1 = e1 * inv;
        float o0 = w0 * v[0][0] + w1 * v[1][0];
        float o1 = w0 * v[0][1] + w1 * v[1][1];
        size_t off = (size_t)(node * 2 + qi) * Dd + h * HDIM + d0;
        __nv_bfloat16 h0 = __float2bfloat16(o0), h1 = __float2bfloat16(o1);
        ushort2 hv, lv;
        hv.x = __bfloat16_as_ushort(h0); hv.y = __bfloat16_as_ushort(h1);
        lv.x = __bfloat16_as_ushort(__float2bfloat16(o0 - __bfloat162float(h0)));
        lv.y = __bfloat16_as_ushort(__float2bfloat16(o1 - __bfloat162float(h1)));
        *(ushort2*)(g_ah + off) = hv;
        *(ushort2*)(g_al + off) = lv;
    }
}

// ---------------- mean over the 2 tokens -> fused hi/lo ----------------------
__global__ void mean_kernel()
{
    int i = blockIdx.x * blockDim.x + threadIdx.x;
    if (i >= Nn * Dd / 4) return;
    int e0 = i * 4;
    int node = e0 / Dd, d = e0 - node * Dd;
    const float* r0 = g_att + (size_t)(node * 2) * Dd + d;
    const float* r1 = g_att + (size_t)(node * 2 + 1) * Dd + d;
    float4 a = *(const float4*)r0, b = *(const float4*)r1;
    float f0 = 0.5f * (a.x + b.x), f1 = 0.5f * (a.y + b.y);
    float f2 = 0.5f * (a.z + b.z), f3 = 0.5f * (a.w + b.w);
    __nv_bfloat16 h0 = __float2bfloat16(f0), h1 = __float2bfloat16(f1);
    __nv_bfloat16 h2 = __float2bfloat16(f2), h3 = __float2bfloat16(f3);
    ushort4 hv, lv;
    hv.x = __bfloat16_as_ushort(h0); hv.y = __bfloat16_as_ushort(h1);
    hv.z = __bfloat16_as_ushort(h2); hv.w = __bfloat16_as_ushort(h3);
    lv.x = __bfloat16_as_ushort(__float2bfloat16(f0 - __bfloat162float(h0)));
    lv.y = __bfloat16_as_ushort(__float2bfloat16(f1 - __bfloat162float(h1)));
    lv.z = __bfloat16_as_ushort(__float2bfloat16(f2 - __bfloat162float(h2)));
    lv.w = __bfloat16_as_ushort(__float2bfloat16(f3 - __bfloat162float(h3)));
    ((ushort4*)g_fh)[i] = hv;
    ((ushort4*)g_fl)[i] = lv;
}

// ---------------- softmax stats + top-16 via segment-max hierarchy ----------
__global__ void topk_kernel(float* __restrict__ Hout)
{
    int row = blockIdx.x;
    extern __shared__ float sh[];                 // Nn floats + 256 segmax
    float* segmax = sh + Nn;
    __shared__ float swv[8];
    __shared__ int swi[8];
    __shared__ float s_bcast;
    __shared__ int s_seg;
    __shared__ float topv[TOPK];
    __shared__ int topi[TOPK];
    const float* srow = g_S + (size_t)row * Nn;
    int tid = threadIdx.x;
    int lane = tid & 31, wid = tid >> 5;

    for (int j = tid; j < Nn; j += 256) sh[j] = srow[j];
    __syncthreads();

    {
        const int base = tid * 32;
        float sm = -INFINITY;
#pragma unroll 8
        for (int i = 0; i < 32; i++)
            sm = fmaxf(sm, sh[base + ((i + tid) & 31)]);
        segmax[tid] = sm;
        float lmax = sm;
#pragma unroll
        for (int o = 16; o > 0; o >>= 1)
            lmax = fmaxf(lmax, __shfl_xor_sync(0xffffffffu, lmax, o));
        if (lane == 0) swv[wid] = lmax;
    }
    __syncthreads();
    if (tid == 0) {
        float m = swv[0];
#pragma unroll
        for (int w = 1; w < 8; w++) m = fmaxf(m, swv[w]);
        s_bcast = m;
    }
    __syncthreads();
    const float rmax = s_bcast;

    float lsum = 0.f;
    for (int j = tid; j < Nn; j += 256) lsum += expf(sh[j] - rmax);
#pragma unroll
    for (int o = 16; o > 0; o >>= 1)
        lsum += __shfl_xor_sync(0xffffffffu, lsum, o);
    if (lane == 0) swv[wid] = lsum;
    __syncthreads();
    if (tid == 0) {
        float s = 0.f;
#pragma unroll
        for (int w = 0; w < 8; w++) s += swv[w];
        s_bcast = 1.f / s;
    }
    __syncthreads();
    const float rinv = s_bcast;

    for (int kk = 0; kk < TOPK; kk++) {
        float v = segmax[tid];
        int idx = tid;
#pragma unroll
        for (int o = 16; o > 0; o >>= 1) {
            float ov = __shfl_xor_sync(0xffffffffu, v, o);
            int oi = __shfl_xor_sync(0xffffffffu, idx, o);
            if (ov > v || (ov == v && oi < idx)) { v = ov; idx = oi; }
        }
        if (lane == 0) { swv[wid] = v; swi[wid] = idx; }
        __syncthreads();
        if (tid == 0) {
            float bv = swv[0]; int bi = swi[0];
#pragma unroll
            for (int w = 1; w < 8; w++)
                if (swv[w] > bv || (swv[w] == bv && swi[w] < bi)) { bv = swv[w]; bi = swi[w]; }
            s_seg = bi;
        }
        __syncthreads();
        const int s = s_seg;
        if (wid == 0) {
            int ei = s * 32 + lane;
            float ev = sh[ei];
            float v2 = ev; int i2 = ei;
#pragma unroll
            for (int o = 16; o > 0; o >>= 1) {
                float ov = __shfl_xor_sync(0xffffffffu, v2, o);
                int oi = __shfl_xor_sync(0xffffffffu, i2, o);
                if (ov > v2 || (ov == v2 && oi < i2)) { v2 = ov; i2 = oi; }
            }
            if (lane == 0) { topv[kk] = v2; topi[kk] = i2; }
            float nv = (ei == i2) ? -INFINITY : ev;
            if (ei == i2) sh[ei] = -INFINITY;
            float mx = nv;
#pragma unroll
            for (int o = 16; o > 0; o >>= 1)
                mx = fmaxf(mx, __shfl_xor_sync(0xffffffffu, mx, o));
            if (lane == 0) segmax[s] = mx;
        }
        __syncthreads();
    }

    if (tid == 0) {
        Hout[(size_t)row * Nn + row] = 1.0f;
#pragma unroll
        for (int kk = 0; kk < TOPK; kk++)
            Hout[(size_t)topi[kk] * Nn + row] = expf(topv[kk] - rmax) * rinv;
    }
}

__global__ void ew_kernel(const float* __restrict__ w2, const float* __restrict__ b2,
                          float* __restrict__ out)
{
    int gt = blockIdx.x * blockDim.x + threadIdx.x;
    int gw = gt >> 5, lane = gt & 31;
    if (gw >= Nn) return;
    const float* hrow = g_hidden + (size_t)gw * (Dd / 2);
    float s = 0.f;
    for (int j = lane; j < Dd / 2; j += 32) s += hrow[j] * w2[j];
#pragma unroll
    for (int o = 16; o > 0; o >>= 1) s += __shfl_xor_sync(0xffffffffu, s, o);
    if (lane == 0) {
        float v = s + b2[0];
        float sig = 1.f / (1.f + expf(-v));
        out[gw] = fmaxf(sig, 1e-8f);
    }
}

// ---------------- launch ------------------------------------------------------
static void do_split(const float* src, uint16_t* hi, uint16_t* lo, size_t n)
{
    int n4 = (int)(n / 4);
    split_kernel<<<(n4 + 255) / 256, 256>>>(src, hi, lo, n4);
}

extern "C" void kernel_launch(void* const* d_in, const int* in_sizes, int n_in,
                              void* d_out, int out_size)
{
    const float* x0    = (const float*)d_in[0];
    const float* x1    = (const float*)d_in[1];
    const float* w_p0  = (const float*)d_in[2];
    const float* b_p0  = (const float*)d_in[3];
    const float* gg0   = (const float*)d_in[4];
    const float* be0   = (const float*)d_in[5];
    const float* w_p1  = (const float*)d_in[6];
    const float* b_p1  = (const float*)d_in[7];
    const float* gg1   = (const float*)d_in[8];
    const float* be1   = (const float*)d_in[9];
    const float* in_w  = (const float*)d_in[10];
    const float* in_b  = (const float*)d_in[11];
    const float* out_w = (const float*)d_in[12];
    const float* out_b = (const float*)d_in[13];
    const float* ew_w1 = (const float*)d_in[14];
    const float* ew_b1 = (const float*)d_in[15];
    const float* ew_w2 = (const float*)d_in[16];
    const float* ew_b2 = (const float*)d_in[17];

    float* H  = (float*)d_out;
    float* ew = H + (size_t)Nn * Nn;

    float *seq, *qkv, *att, *S, *hidden;
    uint16_t *ah, *al, *bh, *bl, *fh, *fl;
    cudaGetSymbolAddress((void**)&seq, g_seq);
    cudaGetSymbolAddress((void**)&qkv, g_qkv);
    cudaGetSymbolAddress((void**)&att, g_att);
    cudaGetSymbolAddress((void**)&S, g_S);
    cudaGetSymbolAddress((void**)&hidden, g_hidden);
    cudaGetSymbolAddress((void**)&ah, g_ah);
    cudaGetSymbolAddress((void**)&al, g_al);
    cudaGetSymbolAddress((void**)&bh, g_bh);
    cudaGetSymbolAddress((void**)&bl, g_bl);
    cudaGetSymbolAddress((void**)&fh, g_fh);
    cudaGetSymbolAddress((void**)&fl, g_fl);

    cudaMemsetAsync(H, 0, (size_t)Nn * Nn * sizeof(float));

    // 1) modality projections: Linear+bias+ReLU, interleaved into seq (fp32)
    do_split(x0, ah, al, (size_t)Nn * Dd);
    do_split(w_p0, bh, bl, (size_t)Dd * Dd);
    tgemm<1, 1><<<dim3(Dd / 128, Nn / 128), 128>>>(ah, al, bh, bl, b_p0, seq, 2 * Dd);
    do_split(x1, ah, al, (size_t)Nn * Dd);
    do_split(w_p1, bh, bl, (size_t)Dd * Dd);
    tgemm<1, 1><<<dim3(Dd / 128, Nn / 128), 128>>>(ah, al, bh, bl, b_p1, seq + Dd, 2 * Dd);

    // 2) LayerNorm -> ah/al (bf16 hi/lo) directly
    ln_kernel<<<2 * Nn, 256>>>(gg0, be0, gg1, be1);

    // 3) qkv projection (A = LN output hi/lo)
    do_split(in_w, bh, bl, (size_t)3 * Dd * Dd);
    tgemm<0, 1><<<dim3(3 * Dd / 128, 2 * Nn / 128), 128>>>(ah, al, bh, bl, in_b, qkv, 3 * Dd);

    // 4) 2-token attention -> ctx hi/lo into ah/al (reuse)
    attn_kernel<<<(Nn * NHEADS * 32) / 256, 256>>>();

    // 5) out-proj
    do_split(out_w, bh, bl, (size_t)Dd * Dd);
    tgemm<0, 1><<<dim3(Dd / 128, 2 * Nn / 128), 128>>>(ah, al, bh, bl, out_b, att, Dd);

    // 6) fuse (mean over 2 tokens) -> fh/fl directly
    mean_kernel<<<(Nn * Dd / 4 + 255) / 256, 256>>>();

    // 7) similarity logits S = fused @ fused^T  (symmetric: upper blocks only)
    tgemm_sym<<<(Nn / 128) * (Nn / 128 + 1) / 2, 128>>>(fh, fl, S);

    // 8) row softmax + top-16 + scatter (segment-max hierarchy)
    topk_kernel<<<Nn, 256, (Nn + 256) * sizeof(float)>>>(H);

    // 9) edge-weight MLP
    do_split(ew_w1, bh, bl, (size_t)(Dd / 2) * Dd);
    tgemm<1, 1><<<dim3((Dd / 2) / 128, Nn / 128), 128>>>(fh, fl, bh, bl, ew_b1, hidden, Dd / 2);
    ew_kernel<<<(Nn * 32) / 256, 256>>>(ew_w2, ew_b2, ew);
}

// round 10
// speedup vs baseline: 1.2700x; 1.0382x over previous
#include <cuda_runtime.h>
#include <cuda_bf16.h>
#include <math.h>
#include <stdint.h>

#define Nn 8192
#define Dd 512
#define KDIM 512
#define NHEADS 8
#define HDIM 64
#define TOPK 16

// ---------------- scratch (static device globals; no allocation) -------------
__device__ float g_seq[2 * Nn * Dd];
__device__ float g_qkv[2 * Nn * 3 * Dd];
__device__ float g_att[2 * Nn * Dd];
__device__ float g_S[(size_t)Nn * Nn];
__device__ float g_hidden[Nn * (Dd / 2)];
__device__ uint16_t g_ah[2 * Nn * Dd], g_al[2 * Nn * Dd];   // act hi/lo (shared path)
__device__ uint16_t g_a1h[Nn * Dd], g_a1l[Nn * Dd];         // proj1 act split
__device__ uint16_t g_wp0h[Dd * Dd], g_wp0l[Dd * Dd];       // per-weight splits
__device__ uint16_t g_wp1h[Dd * Dd], g_wp1l[Dd * Dd];
__device__ uint16_t g_wqh[3 * Dd * Dd], g_wql[3 * Dd * Dd];
__device__ uint16_t g_woh[Dd * Dd], g_wol[Dd * Dd];
__device__ uint16_t g_weh[(Dd / 2) * Dd], g_wel[(Dd / 2) * Dd];
__device__ uint16_t g_fh[Nn * Dd], g_fl[Nn * Dd];           // fused hi/lo

// ============================ PTX helpers ====================================
__device__ __forceinline__ uint32_t smem_u32(const void* p) {
    uint32_t a;
    asm("{ .reg .u64 t; cvta.to.shared.u64 t, %1; cvt.u32.u64 %0, t; }" : "=r"(a) : "l"(p));
    return a;
}
__device__ __forceinline__ void cp16(uint32_t dst, const void* src) {
    asm volatile("cp.async.cg.shared.global [%0], [%1], 16;" :: "r"(dst), "l"(src) : "memory");
}
__device__ __forceinline__ void cp_commit() {
    asm volatile("cp.async.commit_group;" ::: "memory");
}
template <int N> __device__ __forceinline__ void cp_wait() {
    asm volatile("cp.async.wait_group %0;" :: "n"(N) : "memory");
}
__device__ __forceinline__ void ldsm4(uint32_t* r, uint32_t a) {
    asm volatile("ldmatrix.sync.aligned.m8n8.x4.shared.b16 {%0,%1,%2,%3}, [%4];"
                 : "=r"(r[0]), "=r"(r[1]), "=r"(r[2]), "=r"(r[3]) : "r"(a));
}
__device__ __forceinline__ void mma16816(float* c, const uint32_t* a, uint32_t b0, uint32_t b1) {
    asm volatile("mma.sync.aligned.m16n8k16.row.col.f32.bf16.bf16.f32 "
                 "{%0,%1,%2,%3}, {%4,%5,%6,%7}, {%8,%9}, {%0,%1,%2,%3};"
                 : "+f"(c[0]), "+f"(c[1]), "+f"(c[2]), "+f"(c[3])
                 : "r"(a[0]), "r"(a[1]), "r"(a[2]), "r"(a[3]), "r"(b0), "r"(b1));
}

// ======================= warp-MMA NT GEMM (bf16 hi/lo, fp32 acc) =============
// C[M,N] = sum over 3 passes: Ah*Bh^T, Ah*Bl^T, Al*Bh^T.  K == 512 everywhere.
// Tile 128x128, BK=32, double-buffered cp.async.
// 4 warps (128 thr), 2x2 warp grid, 64x64 warp tiles.
template <int RELU, int HAS_BIAS>
__global__ __launch_bounds__(128, 2) void tgemm(
    const uint16_t* __restrict__ Ahp, const uint16_t* __restrict__ Alp,
    const uint16_t* __restrict__ Bhp, const uint16_t* __restrict__ Blp,
    const float* __restrict__ bias, float* __restrict__ C, int ldc)
{
    __shared__ uint16_t sA[2][128 * 32];
    __shared__ uint16_t sB[2][128 * 32];

    const int tid = threadIdx.x;
    const int lane = tid & 31, wid = tid >> 5;
    const int wm = wid & 1;
    const int wn = wid >> 1;
    const int bm = blockIdx.y * 128, bn = blockIdx.x * 128;

    const uint32_t sa0 = smem_u32(&sA[0][0]), sa1 = smem_u32(&sA[1][0]);
    const uint32_t sb0 = smem_u32(&sB[0][0]), sb1 = smem_u32(&sB[1][0]);

    const uint16_t* Asrc[3] = { Ahp, Ahp, Alp };
    const uint16_t* Bsrc[3] = { Bhp, Blp, Bhp };
    const int CPP = KDIM / 32;
    const int NCHK = 3 * CPP;

    uint32_t lsw[4]; size_t lsrc[4];
#pragma unroll
    for (int i = 0; i < 4; i++) {
        int s = tid + 128 * i;
        int r = s >> 2, c = s & 3;
        lsw[i] = r * 64 + (((c ^ ((r >> 1) & 3))) << 4);
        lsrc[i] = (size_t)r * KDIM + c * 8;
    }

    uint32_t offA[2][4], offB[2][4];
#pragma unroll
    for (int kk = 0; kk < 2; kk++) {
#pragma unroll
        for (int f = 0; f < 4; f++) {
            int r = wm * 64 + f * 16 + (lane & 15);
            int c = kk * 2 + (lane >> 4);
            offA[kk][f] = r * 64 + (((c ^ ((r >> 1) & 3))) << 4);
        }
#pragma unroll
        for (int g = 0; g < 4; g++) {
            int r = wn * 64 + g * 16 + (lane & 7) + ((lane >> 4) << 3);
            int c = kk * 2 + ((lane >> 3) & 1);
            offB[kk][g] = r * 64 + (((c ^ ((r >> 1) & 3))) << 4);
        }
    }

    float acc[4][8][4];
#pragma unroll
    for (int f = 0; f < 4; f++)
#pragma unroll
        for (int g = 0; g < 8; g++)
#pragma unroll
            for (int j = 0; j < 4; j++) acc[f][g][j] = 0.f;

    auto load_chunk = [&](int c, int buf) {
        const int pass = c / CPP;
        const int k0 = (c % CPP) * 32;
        const uint16_t* A = Asrc[pass];
        const uint16_t* B = Bsrc[pass];
        const uint32_t da = buf ? sa1 : sa0;
        const uint32_t db = buf ? sb1 : sb0;
#pragma unroll
        for (int i = 0; i < 4; i++) {
            cp16(da + lsw[i], A + (size_t)bm * KDIM + k0 + lsrc[i]);
            cp16(db + lsw[i], B + (size_t)bn * KDIM + k0 + lsrc[i]);
        }
        cp_commit();
    };

    load_chunk(0, 0);

    for (int c = 0; c < NCHK; c++) {
        const int b = c & 1;
        if (c + 1 < NCHK) { load_chunk(c + 1, b ^ 1); cp_wait<1>(); }
        else cp_wait<0>();
        __syncthreads();

        const uint32_t da = b ? sa1 : sa0;
        const uint32_t db = b ? sb1 : sb0;
#pragma unroll
        for (int kk = 0; kk < 2; kk++) {
            uint32_t ra[4][4], rb[4][4];
#pragma unroll
            for (int f = 0; f < 4; f++) ldsm4(ra[f], da + offA[kk][f]);
#pragma unroll
            for (int g = 0; g < 4; g++) ldsm4(rb[g], db + offB[kk][g]);
#pragma unroll
            for (int f = 0; f < 4; f++)
#pragma unroll
                for (int g = 0; g < 4; g++) {
                    mma16816(acc[f][2 * g + 0], ra[f], rb[g][0], rb[g][1]);
                    mma16816(acc[f][2 * g + 1], ra[f], rb[g][2], rb[g][3]);
                }
        }
        __syncthreads();
    }

    const int col0 = bn + wn * 64 + (lane & 3) * 2;
#pragma unroll
    for (int f = 0; f < 4; f++) {
        const int row0 = bm + wm * 64 + f * 16 + (lane >> 2);
#pragma unroll
        for (int g = 0; g < 8; g++) {
            const int col = col0 + g * 8;
            float b0 = 0.f, b1 = 0.f;
            if (HAS_BIAS) { b0 = bias[col]; b1 = bias[col + 1]; }
            float2 v0, v1;
            v0.x = acc[f][g][0] + b0; v0.y = acc[f][g][1] + b1;
            v1.x = acc[f][g][2] + b0; v1.y = acc[f][g][3] + b1;
            if (RELU) {
                v0.x = fmaxf(v0.x, 0.f); v0.y = fmaxf(v0.y, 0.f);
                v1.x = fmaxf(v1.x, 0.f); v1.y = fmaxf(v1.y, 0.f);
            }
            *(float2*)(C + (size_t)row0 * ldc + col) = v0;
            *(float2*)(C + (size_t)(row0 + 8) * ldc + col) = v1;
        }
    }
}

// ============== symmetric variant: S = F*F^T, upper-triangle blocks ==========
__global__ __launch_bounds__(128, 2) void tgemm_sym(
    const uint16_t* __restrict__ Fh, const uint16_t* __restrict__ Fl,
    float* __restrict__ C)
{
    __shared__ __align__(16) uint8_t smraw[32768];
    uint16_t* sAbase = (uint16_t*)smraw;
    uint16_t* sBbase = (uint16_t*)(smraw + 16384);
    float* smT = (float*)smraw;

    const int tid = threadIdx.x;
    const int lane = tid & 31, wid = tid >> 5;
    const int wm = wid & 1;
    const int wn = wid >> 1;

    int t = blockIdx.x;
    int bj = (int)((sqrtf(8.f * t + 1.f) - 1.f) * 0.5f);
    while ((bj + 1) * (bj + 2) / 2 <= t) bj++;
    while (bj * (bj + 1) / 2 > t) bj--;
    int bi = t - bj * (bj + 1) / 2;
    const int bm = bi * 128, bn = bj * 128;

    const uint32_t sa0 = smem_u32(sAbase), sa1 = smem_u32(sAbase + 4096);
    const uint32_t sb0 = smem_u32(sBbase), sb1 = smem_u32(sBbase + 4096);

    const uint16_t* Asrc[3] = { Fh, Fh, Fl };
    const uint16_t* Bsrc[3] = { Fh, Fl, Fh };
    const int CPP = KDIM / 32;
    const int NCHK = 3 * CPP;

    uint32_t lsw[4]; size_t lsrc[4];
#pragma unroll
    for (int i = 0; i < 4; i++) {
        int s = tid + 128 * i;
        int r = s >> 2, c = s & 3;
        lsw[i] = r * 64 + (((c ^ ((r >> 1) & 3))) << 4);
        lsrc[i] = (size_t)r * KDIM + c * 8;
    }

    uint32_t offA[2][4], offB[2][4];
#pragma unroll
    for (int kk = 0; kk < 2; kk++) {
#pragma unroll
        for (int f = 0; f < 4; f++) {
            int r = wm * 64 + f * 16 + (lane & 15);
            int c = kk * 2 + (lane >> 4);
            offA[kk][f] = r * 64 + (((c ^ ((r >> 1) & 3))) << 4);
        }
#pragma unroll
        for (int g = 0; g < 4; g++) {
            int r = wn * 64 + g * 16 + (lane & 7) + ((lane >> 4) << 3);
            int c = kk * 2 + ((lane >> 3) & 1);
            offB[kk][g] = r * 64 + (((c ^ ((r >> 1) & 3))) << 4);
        }
    }

    float acc[4][8][4];
#pragma unroll
    for (int f = 0; f < 4; f++)
#pragma unroll
        for (int g = 0; g < 8; g++)
#pragma unroll
            for (int j = 0; j < 4; j++) acc[f][g][j] = 0.f;

    auto load_chunk = [&](int c, int buf) {
        const int pass = c / CPP;
        const int k0 = (c % CPP) * 32;
        const uint16_t* A = Asrc[pass];
        const uint16_t* B = Bsrc[pass];
        const uint32_t da = buf ? sa1 : sa0;
        const uint32_t db = buf ? sb1 : sb0;
#pragma unroll
        for (int i = 0; i < 4; i++) {
            cp16(da + lsw[i], A + (size_t)bm * KDIM + k0 + lsrc[i]);
            cp16(db + lsw[i], B + (size_t)bn * KDIM + k0 + lsrc[i]);
        }
        cp_commit();
    };

    load_chunk(0, 0);

    for (int c = 0; c < NCHK; c++) {
        const int b = c & 1;
        if (c + 1 < NCHK) { load_chunk(c + 1, b ^ 1); cp_wait<1>(); }
        else cp_wait<0>();
        __syncthreads();

        const uint32_t da = b ? sa1 : sa0;
        const uint32_t db = b ? sb1 : sb0;
#pragma unroll
        for (int kk = 0; kk < 2; kk++) {
            uint32_t ra[4][4], rb[4][4];
#pragma unroll
            for (int f = 0; f < 4; f++) ldsm4(ra[f], da + offA[kk][f]);
#pragma unroll
            for (int g = 0; g < 4; g++) ldsm4(rb[g], db + offB[kk][g]);
#pragma unroll
            for (int f = 0; f < 4; f++)
#pragma unroll
                for (int g = 0; g < 4; g++) {
                    mma16816(acc[f][2 * g + 0], ra[f], rb[g][0], rb[g][1]);
                    mma16816(acc[f][2 * g + 1], ra[f], rb[g][2], rb[g][3]);
                }
        }
        __syncthreads();
    }

    // normal (upper) tile write
    const int col0 = bn + wn * 64 + (lane & 3) * 2;
#pragma unroll
    for (int f = 0; f < 4; f++) {
        const int row0 = bm + wm * 64 + f * 16 + (lane >> 2);
#pragma unroll
        for (int g = 0; g < 8; g++) {
            const int col = col0 + g * 8;
            float2 v0, v1;
            v0.x = acc[f][g][0]; v0.y = acc[f][g][1];
            v1.x = acc[f][g][2]; v1.y = acc[f][g][3];
            *(float2*)(C + (size_t)row0 * Nn + col) = v0;
            *(float2*)(C + (size_t)(row0 + 8) * Nn + col) = v1;
        }
    }

    // mirrored (lower) tile write via smem transpose, coalesced
    if (bi != bj) {
#pragma unroll
        for (int cc = 0; cc < 2; cc++) {
            __syncthreads();
            float* buf = smT + wn * (32 * 128);
#pragma unroll
            for (int gl = 0; gl < 4; gl++) {
                const int g = cc * 4 + gl;
                const int cl = gl * 8 + (lane & 3) * 2;
#pragma unroll
                for (int f = 0; f < 4; f++) {
                    const int r = wm * 64 + f * 16 + (lane >> 2);
                    buf[cl * 128 + r]           = acc[f][g][0];
                    buf[(cl + 1) * 128 + r]     = acc[f][g][1];
                    buf[cl * 128 + r + 8]       = acc[f][g][2];
                    buf[(cl + 1) * 128 + r + 8] = acc[f][g][3];
                }
            }
            __syncthreads();
            for (int idx = tid; idx < 64 * 32; idx += 128) {
                const int rr = idx >> 5;
                const int sg = idx & 31;
                const int b2 = rr >> 5;
                const int cl = rr & 31;
                const int cAbs = bn + b2 * 64 + cc * 32 + cl;
                float4 v = *(float4*)(smT + b2 * (32 * 128) + cl * 128 + sg * 4);
                *(float4*)(C + (size_t)cAbs * Nn + bm + sg * 4) = v;
            }
        }
    }
}

// ---------------- fp32 -> (hi, lo) bf16 split --------------------------------
__global__ void split_kernel(const float* __restrict__ x, uint16_t* __restrict__ hi,
                             uint16_t* __restrict__ lo, int n4)
{
    int i = blockIdx.x * blockDim.x + threadIdx.x;
    if (i >= n4) return;
    float4 v = ((const float4*)x)[i];
    __nv_bfloat16 h0 = __float2bfloat16(v.x), h1 = __float2bfloat16(v.y);
    __nv_bfloat16 h2 = __float2bfloat16(v.z), h3 = __float2bfloat16(v.w);
    __nv_bfloat16 l0 = __float2bfloat16(v.x - __bfloat162float(h0));
    __nv_bfloat16 l1 = __float2bfloat16(v.y - __bfloat162float(h1));
    __nv_bfloat16 l2 = __float2bfloat16(v.z - __bfloat162float(h2));
    __nv_bfloat16 l3 = __float2bfloat16(v.w - __bfloat162float(h3));
    ushort4 hv, lv;
    hv.x = __bfloat16_as_ushort(h0); hv.y = __bfloat16_as_ushort(h1);
    hv.z = __bfloat16_as_ushort(h2); hv.w = __bfloat16_as_ushort(h3);
    lv.x = __bfloat16_as_ushort(l0); lv.y = __bfloat16_as_ushort(l1);
    lv.z = __bfloat16_as_ushort(l2); lv.w = __bfloat16_as_ushort(l3);
    ((ushort4*)hi)[i] = hv;
    ((ushort4*)lo)[i] = lv;
}

// ---------------- LayerNorm -> bf16 hi/lo directly ---------------------------
__global__ void ln_kernel(const float* __restrict__ g0, const float* __restrict__ be0,
                          const float* __restrict__ g1, const float* __restrict__ be1)
{
    int row = blockIdx.x;
    const float* x = g_seq + (size_t)row * Dd;
    int tid = threadIdx.x;
    float v0 = x[tid], v1 = x[tid + 256];
    __shared__ float rs[256], rq[256];
    rs[tid] = v0 + v1;
    rq[tid] = v0 * v0 + v1 * v1;
    __syncthreads();
    for (int st = 128; st > 0; st >>= 1) {
        if (tid < st) { rs[tid] += rs[tid + st]; rq[tid] += rq[tid + st]; }
        __syncthreads();
    }
    float mean = rs[0] * (1.f / Dd);
    float var = rq[0] * (1.f / Dd) - mean * mean;
    float inv = rsqrtf(var + 1e-5f);
    const float* gg = (row & 1) ? g1 : g0;
    const float* bb = (row & 1) ? be1 : be0;
    float y0 = (v0 - mean) * inv * gg[tid] + bb[tid];
    float y1 = (v1 - mean) * inv * gg[tid + 256] + bb[tid + 256];
    size_t base = (size_t)row * Dd;
    __nv_bfloat16 h0 = __float2bfloat16(y0), h1 = __float2bfloat16(y1);
    g_ah[base + tid]       = __bfloat16_as_ushort(h0);
    g_ah[base + tid + 256] = __bfloat16_as_ushort(h1);
    g_al[base + tid]       = __bfloat16_as_ushort(__float2bfloat16(y0 - __bfloat162float(h0)));
    g_al[base + tid + 256] = __bfloat16_as_ushort(__float2bfloat16(y1 - __bfloat162float(h1)));
}

// ---------------- 2-token multihead attention -> ctx hi/lo -------------------
__global__ void attn_kernel()
{
    int gt = blockIdx.x * blockDim.x + threadIdx.x;
    int gw = gt >> 5, lane = gt & 31;
    if (gw >= Nn * NHEADS) return;
    int node = gw >> 3, h = gw & 7;
    const float* base = g_qkv + (size_t)node * 2 * (3 * Dd);
    int d0 = lane * 2;
    float q[2][2], k[2][2], v[2][2];
#pragma unroll
    for (int t = 0; t < 2; t++) {
        const float* r = base + t * (3 * Dd) + h * HDIM;
        float2 qq = *(const float2*)(r + d0);
        float2 kk = *(const float2*)(r + Dd + d0);
        float2 vv = *(const float2*)(r + 2 * Dd + d0);
        q[t][0] = qq.x; q[t][1] = qq.y;
        k[t][0] = kk.x; k[t][1] = kk.y;
        v[t][0] = vv.x; v[t][1] = vv.y;
    }
    float s[2][2];
#pragma unroll
    for (int qi = 0; qi < 2; qi++)
#pragma unroll
        for (int ki = 0; ki < 2; ki++)
            s[qi][ki] = q[qi][0] * k[ki][0] + q[qi][1] * k[ki][1];
#pragma unroll
    for (int o = 16; o > 0; o >>= 1)
#pragma unroll
        for (int qi = 0; qi < 2; qi++)
#pragma unroll
            for (int ki = 0; ki < 2; ki++)
                s[qi][ki] += __shfl_xor_sync(0xffffffffu, s[qi][ki], o);
    const float scale = 0.125f;
#pragma unroll
    for (int qi = 0; qi < 2; qi++) {
        float a0 = s[qi][0] * scale, a1 = s[qi][1] * scale;
        float m = fmaxf(a0, a1);
        float e0 = expf(a0 - m), e1 = expf(a1 - m);
        float inv = 1.f / (e0 + e1);
        float w0 = e0 * inv, w1 = e1 * inv;
        float o0 = w0 * v[0][0] + w1 * v[1][0];
        float o1 = w0 * v[0][1] + w1 * v[1][1];
        size_t off = (size_t)(node * 2 + qi) * Dd + h * HDIM + d0;
        __nv_bfloat16 h0 = __float2bfloat16(o0), h1 = __float2bfloat16(o1);
        ushort2 hv, lv;
        hv.x = __bfloat16_as_ushort(h0); hv.y = __bfloat16_as_ushort(h1);
        lv.x = __bfloat16_as_ushort(__float2bfloat16(o0 - __bfloat162float(h0)));
        lv.y = __bfloat16_as_ushort(__float2bfloat16(o1 - __bfloat162float(h1)));
        *(ushort2*)(g_ah + off) = hv;
        *(ushort2*)(g_al + off) = lv;
    }
}

// ---------------- mean over the 2 tokens -> fused hi/lo ----------------------
__global__ void mean_kernel()
{
    int i = blockIdx.x * blockDim.x + threadIdx.x;
    if (i >= Nn * Dd / 4) return;
    int e0 = i * 4;
    int node = e0 / Dd, d = e0 - node * Dd;
    const float* r0 = g_att + (size_t)(node * 2) * Dd + d;
    const float* r1 = g_att + (size_t)(node * 2 + 1) * Dd + d;
    float4 a = *(const float4*)r0, b = *(const float4*)r1;
    float f0 = 0.5f * (a.x + b.x), f1 = 0.5f * (a.y + b.y);
    float f2 = 0.5f * (a.z + b.z), f3 = 0.5f * (a.w + b.w);
    __nv_bfloat16 h0 = __float2bfloat16(f0), h1 = __float2bfloat16(f1);
    __nv_bfloat16 h2 = __float2bfloat16(f2), h3 = __float2bfloat16(f3);
    ushort4 hv, lv;
    hv.x = __bfloat16_as_ushort(h0); hv.y = __bfloat16_as_ushort(h1);
    hv.z = __bfloat16_as_ushort(h2); hv.w = __bfloat16_as_ushort(h3);
    lv.x = __bfloat16_as_ushort(__float2bfloat16(f0 - __bfloat162float(h0)));
    lv.y = __bfloat16_as_ushort(__float2bfloat16(f1 - __bfloat162float(h1)));
    lv.z = __bfloat16_as_ushort(__float2bfloat16(f2 - __bfloat162float(h2)));
    lv.w = __bfloat16_as_ushort(__float2bfloat16(f3 - __bfloat162float(h3)));
    ((ushort4*)g_fh)[i] = hv;
    ((ushort4*)g_fl)[i] = lv;
}

// ---------------- softmax stats + top-16 via segment-max hierarchy ----------
__global__ void topk_kernel(float* __restrict__ Hout)
{
    int row = blockIdx.x;
    extern __shared__ float sh[];                 // Nn floats + 256 segmax
    float* segmax = sh + Nn;
    __shared__ float swv[8];
    __shared__ int swi[8];
    __shared__ float s_bcast;
    __shared__ int s_seg;
    __shared__ float topv[TOPK];
    __shared__ int topi[TOPK];
    const float* srow = g_S + (size_t)row * Nn;
    int tid = threadIdx.x;
    int lane = tid & 31, wid = tid >> 5;

    for (int j = tid; j < Nn; j += 256) sh[j] = srow[j];
    __syncthreads();

    {
        const int base = tid * 32;
        float sm = -INFINITY;
#pragma unroll 8
        for (int i = 0; i < 32; i++)
            sm = fmaxf(sm, sh[base + ((i + tid) & 31)]);
        segmax[tid] = sm;
        float lmax = sm;
#pragma unroll
        for (int o = 16; o > 0; o >>= 1)
            lmax = fmaxf(lmax, __shfl_xor_sync(0xffffffffu, lmax, o));
        if (lane == 0) swv[wid] = lmax;
    }
    __syncthreads();
    if (tid == 0) {
        float m = swv[0];
#pragma unroll
        for (int w = 1; w < 8; w++) m = fmaxf(m, swv[w]);
        s_bcast = m;
    }
    __syncthreads();
    const float rmax = s_bcast;

    float lsum = 0.f;
    for (int j = tid; j < Nn; j += 256) lsum += expf(sh[j] - rmax);
#pragma unroll
    for (int o = 16; o > 0; o >>= 1)
        lsum += __shfl_xor_sync(0xffffffffu, lsum, o);
    if (lane == 0) swv[wid] = lsum;
    __syncthreads();
    if (tid == 0) {
        float s = 0.f;
#pragma unroll
        for (int w = 0; w < 8; w++) s += swv[w];
        s_bcast = 1.f / s;
    }
    __syncthreads();
    const float rinv = s_bcast;

    for (int kk = 0; kk < TOPK; kk++) {
        float v = segmax[tid];
        int idx = tid;
#pragma unroll
        for (int o = 16; o > 0; o >>= 1) {
            float ov = __shfl_xor_sync(0xffffffffu, v, o);
            int oi = __shfl_xor_sync(0xffffffffu, idx, o);
            if (ov > v || (ov == v && oi < idx)) { v = ov; idx = oi; }
        }
        if (lane == 0) { swv[wid] = v; swi[wid] = idx; }
        __syncthreads();
        if (tid == 0) {
            float bv = swv[0]; int bi = swi[0];
#pragma unroll
            for (int w = 1; w < 8; w++)
                if (swv[w] > bv || (swv[w] == bv && swi[w] < bi)) { bv = swv[w]; bi = swi[w]; }
            s_seg = bi;
        }
        __syncthreads();
        const int s = s_seg;
        if (wid == 0) {
            int ei = s * 32 + lane;
            float ev = sh[ei];
            float v2 = ev; int i2 = ei;
#pragma unroll
            for (int o = 16; o > 0; o >>= 1) {
                float ov = __shfl_xor_sync(0xffffffffu, v2, o);
                int oi = __shfl_xor_sync(0xffffffffu, i2, o);
                if (ov > v2 || (ov == v2 && oi < i2)) { v2 = ov; i2 = oi; }
            }
            if (lane == 0) { topv[kk] = v2; topi[kk] = i2; }
            float nv = (ei == i2) ? -INFINITY : ev;
            if (ei == i2) sh[ei] = -INFINITY;
            float mx = nv;
#pragma unroll
            for (int o = 16; o > 0; o >>= 1)
                mx = fmaxf(mx, __shfl_xor_sync(0xffffffffu, mx, o));
            if (lane == 0) segmax[s] = mx;
        }
        __syncthreads();
    }

    if (tid == 0) {
        Hout[(size_t)row * Nn + row] = 1.0f;
#pragma unroll
        for (int kk = 0; kk < TOPK; kk++)
            Hout[(size_t)topi[kk] * Nn + row] = expf(topv[kk] - rmax) * rinv;
    }
}

__global__ void ew_kernel(const float* __restrict__ w2, const float* __restrict__ b2,
                          float* __restrict__ out)
{
    int gt = blockIdx.x * blockDim.x + threadIdx.x;
    int gw = gt >> 5, lane = gt & 31;
    if (gw >= Nn) return;
    const float* hrow = g_hidden + (size_t)gw * (Dd / 2);
    float s = 0.f;
    for (int j = lane; j < Dd / 2; j += 32) s += hrow[j] * w2[j];
#pragma unroll
    for (int o = 16; o > 0; o >>= 1) s += __shfl_xor_sync(0xffffffffu, s, o);
    if (lane == 0) {
        float v = s + b2[0];
        float sig = 1.f / (1.f + expf(-v));
        out[gw] = fmaxf(sig, 1e-8f);
    }
}

// ---------------- launch ------------------------------------------------------
static void do_split_s(const float* src, uint16_t* hi, uint16_t* lo, size_t n,
                       cudaStream_t st)
{
    int n4 = (int)(n / 4);
    split_kernel<<<(n4 + 255) / 256, 256, 0, st>>>(src, hi, lo, n4);
}

extern "C" void kernel_launch(void* const* d_in, const int* in_sizes, int n_in,
                              void* d_out, int out_size)
{
    const float* x0    = (const float*)d_in[0];
    const float* x1    = (const float*)d_in[1];
    const float* w_p0  = (const float*)d_in[2];
    const float* b_p0  = (const float*)d_in[3];
    const float* gg0   = (const float*)d_in[4];
    const float* be0   = (const float*)d_in[5];
    const float* w_p1  = (const float*)d_in[6];
    const float* b_p1  = (const float*)d_in[7];
    const float* gg1   = (const float*)d_in[8];
    const float* be1   = (const float*)d_in[9];
    const float* in_w  = (const float*)d_in[10];
    const float* in_b  = (const float*)d_in[11];
    const float* out_w = (const float*)d_in[12];
    const float* out_b = (const float*)d_in[13];
    const float* ew_w1 = (const float*)d_in[14];
    const float* ew_b1 = (const float*)d_in[15];
    const float* ew_w2 = (const float*)d_in[16];
    const float* ew_b2 = (const float*)d_in[17];

    float* H  = (float*)d_out;
    float* ew = H + (size_t)Nn * Nn;

    float *seq, *qkv, *att, *S, *hidden;
    uint16_t *ah, *al, *a1h, *a1l, *fh, *fl;
    uint16_t *wp0h, *wp0l, *wp1h, *wp1l, *wqh, *wql, *woh, *wol, *weh, *wel;
    cudaGetSymbolAddress((void**)&seq, g_seq);
    cudaGetSymbolAddress((void**)&qkv, g_qkv);
    cudaGetSymbolAddress((void**)&att, g_att);
    cudaGetSymbolAddress((void**)&S, g_S);
    cudaGetSymbolAddress((void**)&hidden, g_hidden);
    cudaGetSymbolAddress((void**)&ah, g_ah);
    cudaGetSymbolAddress((void**)&al, g_al);
    cudaGetSymbolAddress((void**)&a1h, g_a1h);
    cudaGetSymbolAddress((void**)&a1l, g_a1l);
    cudaGetSymbolAddress((void**)&wp0h, g_wp0h);
    cudaGetSymbolAddress((void**)&wp0l, g_wp0l);
    cudaGetSymbolAddress((void**)&wp1h, g_wp1h);
    cudaGetSymbolAddress((void**)&wp1l, g_wp1l);
    cudaGetSymbolAddress((void**)&wqh, g_wqh);
    cudaGetSymbolAddress((void**)&wql, g_wql);
    cudaGetSymbolAddress((void**)&woh, g_woh);
    cudaGetSymbolAddress((void**)&wol, g_wol);
    cudaGetSymbolAddress((void**)&weh, g_weh);
    cudaGetSymbolAddress((void**)&wel, g_wel);
    cudaGetSymbolAddress((void**)&fh, g_fh);
    cudaGetSymbolAddress((void**)&fl, g_fl);

    // streams/events created ONCE (first call = correctness run, inside the
    // harness's pre-capture baseline) and reused on every later call so the
    // capture/replay cycle allocates nothing.
    static cudaStream_t s1 = nullptr, s2 = nullptr;
    static cudaEvent_t eF = nullptr, eS2 = nullptr, eP1 = nullptr, eM = nullptr, eE = nullptr;
    if (!s1) {
        cudaStreamCreateWithFlags(&s1, cudaStreamNonBlocking);
        cudaStreamCreateWithFlags(&s2, cudaStreamNonBlocking);
        cudaEventCreateWithFlags(&eF,  cudaEventDisableTiming);
        cudaEventCreateWithFlags(&eS2, cudaEventDisableTiming);
        cudaEventCreateWithFlags(&eP1, cudaEventDisableTiming);
        cudaEventCreateWithFlags(&eM,  cudaEventDisableTiming);
        cudaEventCreateWithFlags(&eE,  cudaEventDisableTiming);
    }

    // fork from capture (default) stream
    cudaEventRecord(eF, 0);
    cudaStreamWaitEvent(s1, eF, 0);
    cudaStreamWaitEvent(s2, eF, 0);

    // s2: H memset + weight splits for qkv / out-proj / ew (all input-only)
    cudaMemsetAsync(H, 0, (size_t)Nn * Nn * sizeof(float), s2);
    do_split_s(in_w,  wqh, wql, (size_t)3 * Dd * Dd, s2);
    do_split_s(out_w, woh, wol, (size_t)Dd * Dd, s2);
    do_split_s(ew_w1, weh, wel, (size_t)(Dd / 2) * Dd, s2);
    cudaEventRecord(eS2, s2);

    // s1: modality-1 projection chain (independent buffers)
    do_split_s(x1,   a1h,  a1l,  (size_t)Nn * Dd, s1);
    do_split_s(w_p1, wp1h, wp1l, (size_t)Dd * Dd, s1);
    tgemm<1, 1><<<dim3(Dd / 128, Nn / 128), 128, 0, s1>>>(a1h, a1l, wp1h, wp1l, b_p1, seq + Dd, 2 * Dd);
    cudaEventRecord(eP1, s1);

    // stream 0: modality-0 projection chain (runs concurrently with s1/s2)
    do_split_s(x0,   ah,   al,   (size_t)Nn * Dd, 0);
    do_split_s(w_p0, wp0h, wp0l, (size_t)Dd * Dd, 0);
    tgemm<1, 1><<<dim3(Dd / 128, Nn / 128), 128>>>(ah, al, wp0h, wp0l, b_p0, seq, 2 * Dd);

    // join proj1 + weight splits, then trunk on stream 0
    cudaStreamWaitEvent(0, eP1, 0);
    ln_kernel<<<2 * Nn, 256>>>(gg0, be0, gg1, be1);
    cudaStreamWaitEvent(0, eS2, 0);
    tgemm<0, 1><<<dim3(3 * Dd / 128, 2 * Nn / 128), 128>>>(ah, al, wqh, wql, in_b, qkv, 3 * Dd);
    attn_kernel<<<(Nn * NHEADS * 32) / 256, 256>>>();
    tgemm<0, 1><<<dim3(Dd / 128, 2 * Nn / 128), 128>>>(ah, al, woh, wol, out_b, att, Dd);
    mean_kernel<<<(Nn * Dd / 4 + 255) / 256, 256>>>();
    cudaEventRecord(eM, 0);

    // s1: edge-weight MLP (parallel to sim GEMM + topk)
    cudaStreamWaitEvent(s1, eM, 0);
    tgemm<1, 1><<<dim3((Dd / 2) / 128, Nn / 128), 128, 0, s1>>>(fh, fl, weh, wel, ew_b1, hidden, Dd / 2);
    ew_kernel<<<(Nn * 32) / 256, 256, 0, s1>>>(ew_w2, ew_b2, ew);
    cudaEventRecord(eE, s1);

    // stream 0: similarity GEMM (symmetric) + softmax/topk/scatter
    tgemm_sym<<<(Nn / 128) * (Nn / 128 + 1) / 2, 128>>>(fh, fl, S);
    topk_kernel<<<Nn, 256, (Nn + 256) * sizeof(float)>>>(H);

    // join ew branch back into capture stream
    cudaStreamWaitEvent(0, eE, 0);
}

// round 11
// speedup vs baseline: 1.5780x; 1.2425x over previous
#include <cuda_runtime.h>
#include <cuda_fp16.h>
#include <math.h>
#include <stdint.h>

#define Nn 8192
#define Dd 512
#define KDIM 512
#define NHEADS 8
#define HDIM 64
#define TOPK 16

// ---------------- scratch (static device globals; no allocation) -------------
__device__ float g_seq[2 * Nn * Dd];
__device__ float g_qkv[2 * Nn * 3 * Dd];
__device__ float g_att[2 * Nn * Dd];
__device__ float g_S[(size_t)Nn * Nn];
__device__ float g_hidden[Nn * (Dd / 2)];
__device__ uint16_t g_ah[2 * Nn * Dd], g_al[2 * Nn * Dd];   // act hi/lo (fp16)
__device__ uint16_t g_a1h[Nn * Dd], g_a1l[Nn * Dd];         // proj1 act split
__device__ uint16_t g_wp0h[Dd * Dd], g_wp0l[Dd * Dd];       // per-weight splits
__device__ uint16_t g_wp1h[Dd * Dd], g_wp1l[Dd * Dd];
__device__ uint16_t g_wqh[3 * Dd * Dd], g_wql[3 * Dd * Dd];
__device__ uint16_t g_woh[Dd * Dd], g_wol[Dd * Dd];
__device__ uint16_t g_weh[(Dd / 2) * Dd], g_wel[(Dd / 2) * Dd];
__device__ uint16_t g_fh[Nn * Dd], g_fl[Nn * Dd];           // fused hi/lo

// ============================ PTX helpers ====================================
__device__ __forceinline__ uint32_t smem_u32(const void* p) {
    uint32_t a;
    asm("{ .reg .u64 t; cvta.to.shared.u64 t, %1; cvt.u32.u64 %0, t; }" : "=r"(a) : "l"(p));
    return a;
}
__device__ __forceinline__ void cp16(uint32_t dst, const void* src) {
    asm volatile("cp.async.cg.shared.global [%0], [%1], 16;" :: "r"(dst), "l"(src) : "memory");
}
__device__ __forceinline__ void cp_commit() {
    asm volatile("cp.async.commit_group;" ::: "memory");
}
template <int N> __device__ __forceinline__ void cp_wait() {
    asm volatile("cp.async.wait_group %0;" :: "n"(N) : "memory");
}
__device__ __forceinline__ void ldsm4(uint32_t* r, uint32_t a) {
    asm volatile("ldmatrix.sync.aligned.m8n8.x4.shared.b16 {%0,%1,%2,%3}, [%4];"
                 : "=r"(r[0]), "=r"(r[1]), "=r"(r[2]), "=r"(r[3]) : "r"(a));
}
__device__ __forceinline__ void mma16816(float* c, const uint32_t* a, uint32_t b0, uint32_t b1) {
    asm volatile("mma.sync.aligned.m16n8k16.row.col.f32.f16.f16.f32 "
                 "{%0,%1,%2,%3}, {%4,%5,%6,%7}, {%8,%9}, {%0,%1,%2,%3};"
                 : "+f"(c[0]), "+f"(c[1]), "+f"(c[2]), "+f"(c[3])
                 : "r"(a[0]), "r"(a[1]), "r"(a[2]), "r"(a[3]), "r"(b0), "r"(b1));
}

// ======================= warp-MMA NT GEMM (fp16 hi/lo, fp32 acc) =============
// C[M,N] = Ah*Bh^T + Ah*Bl^T  (2-pass fp16 compensation; dropped Al*Bh term
// contributes ~1.4e-4 rms relative).  K == 512 everywhere.
// Tile 128x128, BK=32, double-buffered cp.async, 4 warps 2x2 (64x64 per warp).
template <int RELU, int HAS_BIAS>
__global__ __launch_bounds__(128, 2) void tgemm(
    const uint16_t* __restrict__ Ahp, const uint16_t* __restrict__ Alp,
    const uint16_t* __restrict__ Bhp, const uint16_t* __restrict__ Blp,
    const float* __restrict__ bias, float* __restrict__ C, int ldc)
{
    __shared__ uint16_t sA[2][128 * 32];
    __shared__ uint16_t sB[2][128 * 32];

    const int tid = threadIdx.x;
    const int lane = tid & 31, wid = tid >> 5;
    const int wm = wid & 1;
    const int wn = wid >> 1;
    const int bm = blockIdx.y * 128, bn = blockIdx.x * 128;

    const uint32_t sa0 = smem_u32(&sA[0][0]), sa1 = smem_u32(&sA[1][0]);
    const uint32_t sb0 = smem_u32(&sB[0][0]), sb1 = smem_u32(&sB[1][0]);

    const uint16_t* Asrc[2] = { Ahp, Ahp };
    const uint16_t* Bsrc[2] = { Bhp, Blp };
    const int CPP = KDIM / 32;       // 16
    const int NCHK = 2 * CPP;        // 32

    uint32_t lsw[4]; size_t lsrc[4];
#pragma unroll
    for (int i = 0; i < 4; i++) {
        int s = tid + 128 * i;
        int r = s >> 2, c = s & 3;
        lsw[i] = r * 64 + (((c ^ ((r >> 1) & 3))) << 4);
        lsrc[i] = (size_t)r * KDIM + c * 8;
    }

    uint32_t offA[2][4], offB[2][4];
#pragma unroll
    for (int kk = 0; kk < 2; kk++) {
#pragma unroll
        for (int f = 0; f < 4; f++) {
            int r = wm * 64 + f * 16 + (lane & 15);
            int c = kk * 2 + (lane >> 4);
            offA[kk][f] = r * 64 + (((c ^ ((r >> 1) & 3))) << 4);
        }
#pragma unroll
        for (int g = 0; g < 4; g++) {
            int r = wn * 64 + g * 16 + (lane & 7) + ((lane >> 4) << 3);
            int c = kk * 2 + ((lane >> 3) & 1);
            offB[kk][g] = r * 64 + (((c ^ ((r >> 1) & 3))) << 4);
        }
    }

    float acc[4][8][4];
#pragma unroll
    for (int f = 0; f < 4; f++)
#pragma unroll
        for (int g = 0; g < 8; g++)
#pragma unroll
            for (int j = 0; j < 4; j++) acc[f][g][j] = 0.f;

    auto load_chunk = [&](int c, int buf) {
        const int pass = c / CPP;
        const int k0 = (c % CPP) * 32;
        const uint16_t* A = Asrc[pass];
        const uint16_t* B = Bsrc[pass];
        const uint32_t da = buf ? sa1 : sa0;
        const uint32_t db = buf ? sb1 : sb0;
#pragma unroll
        for (int i = 0; i < 4; i++) {
            cp16(da + lsw[i], A + (size_t)bm * KDIM + k0 + lsrc[i]);
            cp16(db + lsw[i], B + (size_t)bn * KDIM + k0 + lsrc[i]);
        }
        cp_commit();
    };

    load_chunk(0, 0);

    for (int c = 0; c < NCHK; c++) {
        const int b = c & 1;
        if (c + 1 < NCHK) { load_chunk(c + 1, b ^ 1); cp_wait<1>(); }
        else cp_wait<0>();
        __syncthreads();

        const uint32_t da = b ? sa1 : sa0;
        const uint32_t db = b ? sb1 : sb0;
#pragma unroll
        for (int kk = 0; kk < 2; kk++) {
            uint32_t ra[4][4], rb[4][4];
#pragma unroll
            for (int f = 0; f < 4; f++) ldsm4(ra[f], da + offA[kk][f]);
#pragma unroll
            for (int g = 0; g < 4; g++) ldsm4(rb[g], db + offB[kk][g]);
#pragma unroll
            for (int f = 0; f < 4; f++)
#pragma unroll
                for (int g = 0; g < 4; g++) {
                    mma16816(acc[f][2 * g + 0], ra[f], rb[g][0], rb[g][1]);
                    mma16816(acc[f][2 * g + 1], ra[f], rb[g][2], rb[g][3]);
                }
        }
        __syncthreads();
    }

    const int col0 = bn + wn * 64 + (lane & 3) * 2;
#pragma unroll
    for (int f = 0; f < 4; f++) {
        const int row0 = bm + wm * 64 + f * 16 + (lane >> 2);
#pragma unroll
        for (int g = 0; g < 8; g++) {
            const int col = col0 + g * 8;
            float b0 = 0.f, b1 = 0.f;
            if (HAS_BIAS) { b0 = bias[col]; b1 = bias[col + 1]; }
            float2 v0, v1;
            v0.x = acc[f][g][0] + b0; v0.y = acc[f][g][1] + b1;
            v1.x = acc[f][g][2] + b0; v1.y = acc[f][g][3] + b1;
            if (RELU) {
                v0.x = fmaxf(v0.x, 0.f); v0.y = fmaxf(v0.y, 0.f);
                v1.x = fmaxf(v1.x, 0.f); v1.y = fmaxf(v1.y, 0.f);
            }
            *(float2*)(C + (size_t)row0 * ldc + col) = v0;
            *(float2*)(C + (size_t)(row0 + 8) * ldc + col) = v1;
        }
    }
}

// ============== symmetric variant: S = F*F^T, upper-triangle blocks ==========
__global__ __launch_bounds__(128, 2) void tgemm_sym(
    const uint16_t* __restrict__ Fh, const uint16_t* __restrict__ Fl,
    float* __restrict__ C)
{
    __shared__ __align__(16) uint8_t smraw[32768];
    uint16_t* sAbase = (uint16_t*)smraw;
    uint16_t* sBbase = (uint16_t*)(smraw + 16384);
    float* smT = (float*)smraw;

    const int tid = threadIdx.x;
    const int lane = tid & 31, wid = tid >> 5;
    const int wm = wid & 1;
    const int wn = wid >> 1;

    int t = blockIdx.x;
    int bj = (int)((sqrtf(8.f * t + 1.f) - 1.f) * 0.5f);
    while ((bj + 1) * (bj + 2) / 2 <= t) bj++;
    while (bj * (bj + 1) / 2 > t) bj--;
    int bi = t - bj * (bj + 1) / 2;
    const int bm = bi * 128, bn = bj * 128;

    const uint32_t sa0 = smem_u32(sAbase), sa1 = smem_u32(sAbase + 4096);
    const uint32_t sb0 = smem_u32(sBbase), sb1 = smem_u32(sBbase + 4096);

    const uint16_t* Asrc[2] = { Fh, Fh };
    const uint16_t* Bsrc[2] = { Fh, Fl };
    const int CPP = KDIM / 32;
    const int NCHK = 2 * CPP;

    uint32_t lsw[4]; size_t lsrc[4];
#pragma unroll
    for (int i = 0; i < 4; i++) {
        int s = tid + 128 * i;
        int r = s >> 2, c = s & 3;
        lsw[i] = r * 64 + (((c ^ ((r >> 1) & 3))) << 4);
        lsrc[i] = (size_t)r * KDIM + c * 8;
    }

    uint32_t offA[2][4], offB[2][4];
#pragma unroll
    for (int kk = 0; kk < 2; kk++) {
#pragma unroll
        for (int f = 0; f < 4; f++) {
            int r = wm * 64 + f * 16 + (lane & 15);
            int c = kk * 2 + (lane >> 4);
            offA[kk][f] = r * 64 + (((c ^ ((r >> 1) & 3))) << 4);
        }
#pragma unroll
        for (int g = 0; g < 4; g++) {
            int r = wn * 64 + g * 16 + (lane & 7) + ((lane >> 4) << 3);
            int c = kk * 2 + ((lane >> 3) & 1);
            offB[kk][g] = r * 64 + (((c ^ ((r >> 1) & 3))) << 4);
        }
    }

    float acc[4][8][4];
#pragma unroll
    for (int f = 0; f < 4; f++)
#pragma unroll
        for (int g = 0; g < 8; g++)
#pragma unroll
            for (int j = 0; j < 4; j++) acc[f][g][j] = 0.f;

    auto load_chunk = [&](int c, int buf) {
        const int pass = c / CPP;
        const int k0 = (c % CPP) * 32;
        const uint16_t* A = Asrc[pass];
        const uint16_t* B = Bsrc[pass];
        const uint32_t da = buf ? sa1 : sa0;
        const uint32_t db = buf ? sb1 : sb0;
#pragma unroll
        for (int i = 0; i < 4; i++) {
            cp16(da + lsw[i], A + (size_t)bm * KDIM + k0 + lsrc[i]);
            cp16(db + lsw[i], B + (size_t)bn * KDIM + k0 + lsrc[i]);
        }
        cp_commit();
    };

    load_chunk(0, 0);

    for (int c = 0; c < NCHK; c++) {
        const int b = c & 1;
        if (c + 1 < NCHK) { load_chunk(c + 1, b ^ 1); cp_wait<1>(); }
        else cp_wait<0>();
        __syncthreads();

        const uint32_t da = b ? sa1 : sa0;
        const uint32_t db = b ? sb1 : sb0;
#pragma unroll
        for (int kk = 0; kk < 2; kk++) {
            uint32_t ra[4][4], rb[4][4];
#pragma unroll
            for (int f = 0; f < 4; f++) ldsm4(ra[f], da + offA[kk][f]);
#pragma unroll
            for (int g = 0; g < 4; g++) ldsm4(rb[g], db + offB[kk][g]);
#pragma unroll
            for (int f = 0; f < 4; f++)
#pragma unroll
                for (int g = 0; g < 4; g++) {
                    mma16816(acc[f][2 * g + 0], ra[f], rb[g][0], rb[g][1]);
                    mma16816(acc[f][2 * g + 1], ra[f], rb[g][2], rb[g][3]);
                }
        }
        __syncthreads();
    }

    // normal (upper) tile write
    const int col0 = bn + wn * 64 + (lane & 3) * 2;
#pragma unroll
    for (int f = 0; f < 4; f++) {
        const int row0 = bm + wm * 64 + f * 16 + (lane >> 2);
#pragma unroll
        for (int g = 0; g < 8; g++) {
            const int col = col0 + g * 8;
            float2 v0, v1;
            v0.x = acc[f][g][0]; v0.y = acc[f][g][1];
            v1.x = acc[f][g][2]; v1.y = acc[f][g][3];
            *(float2*)(C + (size_t)row0 * Nn + col) = v0;
            *(float2*)(C + (size_t)(row0 + 8) * Nn + col) = v1;
        }
    }

    // mirrored (lower) tile write via smem transpose, coalesced
    if (bi != bj) {
#pragma unroll
        for (int cc = 0; cc < 2; cc++) {
            __syncthreads();
            float* buf = smT + wn * (32 * 128);
#pragma unroll
            for (int gl = 0; gl < 4; gl++) {
                const int g = cc * 4 + gl;
                const int cl = gl * 8 + (lane & 3) * 2;
#pragma unroll
                for (int f = 0; f < 4; f++) {
                    const int r = wm * 64 + f * 16 + (lane >> 2);
                    buf[cl * 128 + r]           = acc[f][g][0];
                    buf[(cl + 1) * 128 + r]     = acc[f][g][1];
                    buf[cl * 128 + r + 8]       = acc[f][g][2];
                    buf[(cl + 1) * 128 + r + 8] = acc[f][g][3];
                }
            }
            __syncthreads();
            for (int idx = tid; idx < 64 * 32; idx += 128) {
                const int rr = idx >> 5;
                const int sg = idx & 31;
                const int b2 = rr >> 5;
                const int cl = rr & 31;
                const int cAbs = bn + b2 * 64 + cc * 32 + cl;
                float4 v = *(float4*)(smT + b2 * (32 * 128) + cl * 128 + sg * 4);
                *(float4*)(C + (size_t)cAbs * Nn + bm + sg * 4) = v;
            }
        }
    }
}

// ---------------- fp32 -> (hi, lo) fp16 split --------------------------------
__global__ void split_kernel(const float* __restrict__ x, uint16_t* __restrict__ hi,
                             uint16_t* __restrict__ lo, int n4)
{
    int i = blockIdx.x * blockDim.x + threadIdx.x;
    if (i >= n4) return;
    float4 v = ((const float4*)x)[i];
    __half h0 = __float2half_rn(v.x), h1 = __float2half_rn(v.y);
    __half h2 = __float2half_rn(v.z), h3 = __float2half_rn(v.w);
    __half l0 = __float2half_rn(v.x - __half2float(h0));
    __half l1 = __float2half_rn(v.y - __half2float(h1));
    __half l2 = __float2half_rn(v.z - __half2float(h2));
    __half l3 = __float2half_rn(v.w - __half2float(h3));
    ushort4 hv, lv;
    hv.x = __half_as_ushort(h0); hv.y = __half_as_ushort(h1);
    hv.z = __half_as_ushort(h2); hv.w = __half_as_ushort(h3);
    lv.x = __half_as_ushort(l0); lv.y = __half_as_ushort(l1);
    lv.z = __half_as_ushort(l2); lv.w = __half_as_ushort(l3);
    ((ushort4*)hi)[i] = hv;
    ((ushort4*)lo)[i] = lv;
}

// ---------------- LayerNorm -> fp16 hi/lo directly ---------------------------
__global__ void ln_kernel(const float* __restrict__ g0, const float* __restrict__ be0,
                          const float* __restrict__ g1, const float* __restrict__ be1)
{
    int row = blockIdx.x;
    const float* x = g_seq + (size_t)row * Dd;
    int tid = threadIdx.x;
    float v0 = x[tid], v1 = x[tid + 256];
    __shared__ float rs[256], rq[256];
    rs[tid] = v0 + v1;
    rq[tid] = v0 * v0 + v1 * v1;
    __syncthreads();
    for (int st = 128; st > 0; st >>= 1) {
        if (tid < st) { rs[tid] += rs[tid + st]; rq[tid] += rq[tid + st]; }
        __syncthreads();
    }
    float mean = rs[0] * (1.f / Dd);
    float var = rq[0] * (1.f / Dd) - mean * mean;
    float inv = rsqrtf(var + 1e-5f);
    const float* gg = (row & 1) ? g1 : g0;
    const float* bb = (row & 1) ? be1 : be0;
    float y0 = (v0 - mean) * inv * gg[tid] + bb[tid];
    float y1 = (v1 - mean) * inv * gg[tid + 256] + bb[tid + 256];
    size_t base = (size_t)row * Dd;
    __half h0 = __float2half_rn(y0), h1 = __float2half_rn(y1);
    g_ah[base + tid]       = __half_as_ushort(h0);
    g_ah[base + tid + 256] = __half_as_ushort(h1);
    g_al[base + tid]       = __half_as_ushort(__float2half_rn(y0 - __half2float(h0)));
    g_al[base + tid + 256] = __half_as_ushort(__float2half_rn(y1 - __half2float(h1)));
}

// ---------------- 2-token multihead attention -> ctx hi/lo -------------------
__global__ void attn_kernel()
{
    int gt = blockIdx.x * blockDim.x + threadIdx.x;
    int gw = gt >> 5, lane = gt & 31;
    if (gw >= Nn * NHEADS) return;
    int node = gw >> 3, h = gw & 7;
    const float* base = g_qkv + (size_t)node * 2 * (3 * Dd);
    int d0 = lane * 2;
    float q[2][2], k[2][2], v[2][2];
#pragma unroll
    for (int t = 0; t < 2; t++) {
        const float* r = base + t * (3 * Dd) + h * HDIM;
        float2 qq = *(const float2*)(r + d0);
        float2 kk = *(const float2*)(r + Dd + d0);
        float2 vv = *(const float2*)(r + 2 * Dd + d0);
        q[t][0] = qq.x; q[t][1] = qq.y;
        k[t][0] = kk.x; k[t][1] = kk.y;
        v[t][0] = vv.x; v[t][1] = vv.y;
    }
    float s[2][2];
#pragma unroll
    for (int qi = 0; qi < 2; qi++)
#pragma unroll
        for (int ki = 0; ki < 2; ki++)
            s[qi][ki] = q[qi][0] * k[ki][0] + q[qi][1] * k[ki][1];
#pragma unroll
    for (int o = 16; o > 0; o >>= 1)
#pragma unroll
        for (int qi = 0; qi < 2; qi++)
#pragma unroll
            for (int ki = 0; ki < 2; ki++)
                s[qi][ki] += __shfl_xor_sync(0xffffffffu, s[qi][ki], o);
    const float scale = 0.125f;
#pragma unroll
    for (int qi = 0; qi < 2; qi++) {
        float a0 = s[qi][0] * scale, a1 = s[qi][1] * scale;
        float m = fmaxf(a0, a1);
        float e0 = expf(a0 - m), e1 = expf(a1 - m);
        float inv = 1.f / (e0 + e1);
        float w0 = e0 * inv, w1 = e1 * inv;
        float o0 = w0 * v[0][0] + w1 * v[1][0];
        float o1 = w0 * v[0][1] + w1 * v[1][1];
        size_t off = (size_t)(node * 2 + qi) * Dd + h * HDIM + d0;
        __half h0 = __float2half_rn(o0), h1 = __float2half_rn(o1);
        ushort2 hv, lv;
        hv.x = __half_as_ushort(h0); hv.y = __half_as_ushort(h1);
        lv.x = __half_as_ushort(__float2half_rn(o0 - __half2float(h0)));
        lv.y = __half_as_ushort(__float2half_rn(o1 - __half2float(h1)));
        *(ushort2*)(g_ah + off) = hv;
        *(ushort2*)(g_al + off) = lv;
    }
}

// ---------------- mean over the 2 tokens -> fused hi/lo ----------------------
__global__ void mean_kernel()
{
    int i = blockIdx.x * blockDim.x + threadIdx.x;
    if (i >= Nn * Dd / 4) return;
    int e0 = i * 4;
    int node = e0 / Dd, d = e0 - node * Dd;
    const float* r0 = g_att + (size_t)(node * 2) * Dd + d;
    const float* r1 = g_att + (size_t)(node * 2 + 1) * Dd + d;
    float4 a = *(const float4*)r0, b = *(const float4*)r1;
    float f0 = 0.5f * (a.x + b.x), f1 = 0.5f * (a.y + b.y);
    float f2 = 0.5f * (a.z + b.z), f3 = 0.5f * (a.w + b.w);
    __half h0 = __float2half_rn(f0), h1 = __float2half_rn(f1);
    __half h2 = __float2half_rn(f2), h3 = __float2half_rn(f3);
    ushort4 hv, lv;
    hv.x = __half_as_ushort(h0); hv.y = __half_as_ushort(h1);
    hv.z = __half_as_ushort(h2); hv.w = __half_as_ushort(h3);
    lv.x = __half_as_ushort(__float2half_rn(f0 - __half2float(h0)));
    lv.y = __half_as_ushort(__float2half_rn(f1 - __half2float(h1)));
    lv.z = __half_as_ushort(__float2half_rn(f2 - __half2float(h2)));
    lv.w = __half_as_ushort(__float2half_rn(f3 - __half2float(h3)));
    ((ushort4*)g_fh)[i] = hv;
    ((ushort4*)g_fl)[i] = lv;
}

// ---------------- softmax stats + top-16 via segment-max hierarchy ----------
__global__ void topk_kernel(float* __restrict__ Hout)
{
    int row = blockIdx.x;
    extern __shared__ float sh[];                 // Nn floats + 256 segmax
    float* segmax = sh + Nn;
    __shared__ float swv[8];
    __shared__ int swi[8];
    __shared__ float s_bcast;
    __shared__ int s_seg;
    __shared__ float topv[TOPK];
    __shared__ int topi[TOPK];
    const float* srow = g_S + (size_t)row * Nn;
    int tid = threadIdx.x;
    int lane = tid & 31, wid = tid >> 5;

    for (int j = tid; j < Nn; j += 256) sh[j] = srow[j];
    __syncthreads();

    {
        const int base = tid * 32;
        float sm = -INFINITY;
#pragma unroll 8
        for (int i = 0; i < 32; i++)
            sm = fmaxf(sm, sh[base + ((i + tid) & 31)]);
        segmax[tid] = sm;
        float lmax = sm;
#pragma unroll
        for (int o = 16; o > 0; o >>= 1)
            lmax = fmaxf(lmax, __shfl_xor_sync(0xffffffffu, lmax, o));
        if (lane == 0) swv[wid] = lmax;
    }
    __syncthreads();
    if (tid == 0) {
        float m = swv[0];
#pragma unroll
        for (int w = 1; w < 8; w++) m = fmaxf(m, swv[w]);
        s_bcast = m;
    }
    __syncthreads();
    const float rmax = s_bcast;

    float lsum = 0.f;
    for (int j = tid; j < Nn; j += 256) lsum += expf(sh[j] - rmax);
#pragma unroll
    for (int o = 16; o > 0; o >>= 1)
        lsum += __shfl_xor_sync(0xffffffffu, lsum, o);
    if (lane == 0) swv[wid] = lsum;
    __syncthreads();
    if (tid == 0) {
        float s = 0.f;
#pragma unroll
        for (int w = 0; w < 8; w++) s += swv[w];
        s_bcast = 1.f / s;
    }
    __syncthreads();
    const float rinv = s_bcast;

    for (int kk = 0; kk < TOPK; kk++) {
        float v = segmax[tid];
        int idx = tid;
#pragma unroll
        for (int o = 16; o > 0; o >>= 1) {
            float ov = __shfl_xor_sync(0xffffffffu, v, o);
            int oi = __shfl_xor_sync(0xffffffffu, idx, o);
            if (ov > v || (ov == v && oi < idx)) { v = ov; idx = oi; }
        }
        if (lane == 0) { swv[wid] = v; swi[wid] = idx; }
        __syncthreads();
        if (tid == 0) {
            float bv = swv[0]; int bi = swi[0];
#pragma unroll
            for (int w = 1; w < 8; w++)
                if (swv[w] > bv || (swv[w] == bv && swi[w] < bi)) { bv = swv[w]; bi = swi[w]; }
            s_seg = bi;
        }
        __syncthreads();
        const int s = s_seg;
        if (wid == 0) {
            int ei = s * 32 + lane;
            float ev = sh[ei];
            float v2 = ev; int i2 = ei;
#pragma unroll
            for (int o = 16; o > 0; o >>= 1) {
                float ov = __shfl_xor_sync(0xffffffffu, v2, o);
                int oi = __shfl_xor_sync(0xffffffffu, i2, o);
                if (ov > v2 || (ov == v2 && oi < i2)) { v2 = ov; i2 = oi; }
            }
            if (lane == 0) { topv[kk] = v2; topi[kk] = i2; }
            float nv = (ei == i2) ? -INFINITY : ev;
            if (ei == i2) sh[ei] = -INFINITY;
            float mx = nv;
#pragma unroll
            for (int o = 16; o > 0; o >>= 1)
                mx = fmaxf(mx, __shfl_xor_sync(0xffffffffu, mx, o));
            if (lane == 0) segmax[s] = mx;
        }
        __syncthreads();
    }

    if (tid == 0) {
        Hout[(size_t)row * Nn + row] = 1.0f;
#pragma unroll
        for (int kk = 0; kk < TOPK; kk++)
            Hout[(size_t)topi[kk] * Nn + row] = expf(topv[kk] - rmax) * rinv;
    }
}

__global__ void ew_kernel(const float* __restrict__ w2, const float* __restrict__ b2,
                          float* __restrict__ out)
{
    int gt = blockIdx.x * blockDim.x + threadIdx.x;
    int gw = gt >> 5, lane = gt & 31;
    if (gw >= Nn) return;
    const float* hrow = g_hidden + (size_t)gw * (Dd / 2);
    float s = 0.f;
    for (int j = lane; j < Dd / 2; j += 32) s += hrow[j] * w2[j];
#pragma unroll
    for (int o = 16; o > 0; o >>= 1) s += __shfl_xor_sync(0xffffffffu, s, o);
    if (lane == 0) {
        float v = s + b2[0];
        float sig = 1.f / (1.f + expf(-v));
        out[gw] = fmaxf(sig, 1e-8f);
    }
}

// ---------------- launch ------------------------------------------------------
static void do_split_s(const float* src, uint16_t* hi, uint16_t* lo, size_t n,
                       cudaStream_t st)
{
    int n4 = (int)(n / 4);
    split_kernel<<<(n4 + 255) / 256, 256, 0, st>>>(src, hi, lo, n4);
}

extern "C" void kernel_launch(void* const* d_in, const int* in_sizes, int n_in,
                              void* d_out, int out_size)
{
    const float* x0    = (const float*)d_in[0];
    const float* x1    = (const float*)d_in[1];
    const float* w_p0  = (const float*)d_in[2];
    const float* b_p0  = (const float*)d_in[3];
    const float* gg0   = (const float*)d_in[4];
    const float* be0   = (const float*)d_in[5];
    const float* w_p1  = (const float*)d_in[6];
    const float* b_p1  = (const float*)d_in[7];
    const float* gg1   = (const float*)d_in[8];
    const float* be1   = (const float*)d_in[9];
    const float* in_w  = (const float*)d_in[10];
    const float* in_b  = (const float*)d_in[11];
    const float* out_w = (const float*)d_in[12];
    const float* out_b = (const float*)d_in[13];
    const float* ew_w1 = (const float*)d_in[14];
    const float* ew_b1 = (const float*)d_in[15];
    const float* ew_w2 = (const float*)d_in[16];
    const float* ew_b2 = (const float*)d_in[17];

    float* H  = (float*)d_out;
    float* ew = H + (size_t)Nn * Nn;

    float *seq, *qkv, *att, *S, *hidden;
    uint16_t *ah, *al, *a1h, *a1l, *fh, *fl;
    uint16_t *wp0h, *wp0l, *wp1h, *wp1l, *wqh, *wql, *woh, *wol, *weh, *wel;
    cudaGetSymbolAddress((void**)&seq, g_seq);
    cudaGetSymbolAddress((void**)&qkv, g_qkv);
    cudaGetSymbolAddress((void**)&att, g_att);
    cudaGetSymbolAddress((void**)&S, g_S);
    cudaGetSymbolAddress((void**)&hidden, g_hidden);
    cudaGetSymbolAddress((void**)&ah, g_ah);
    cudaGetSymbolAddress((void**)&al, g_al);
    cudaGetSymbolAddress((void**)&a1h, g_a1h);
    cudaGetSymbolAddress((void**)&a1l, g_a1l);
    cudaGetSymbolAddress((void**)&wp0h, g_wp0h);
    cudaGetSymbolAddress((void**)&wp0l, g_wp0l);
    cudaGetSymbolAddress((void**)&wp1h, g_wp1h);
    cudaGetSymbolAddress((void**)&wp1l, g_wp1l);
    cudaGetSymbolAddress((void**)&wqh, g_wqh);
    cudaGetSymbolAddress((void**)&wql, g_wql);
    cudaGetSymbolAddress((void**)&woh, g_woh);
    cudaGetSymbolAddress((void**)&wol, g_wol);
    cudaGetSymbolAddress((void**)&weh, g_weh);
    cudaGetSymbolAddress((void**)&wel, g_wel);
    cudaGetSymbolAddress((void**)&fh, g_fh);
    cudaGetSymbolAddress((void**)&fl, g_fl);

    // streams/events created ONCE (first call = correctness run, inside the
    // harness's pre-capture baseline) and reused on every later call.
    static cudaStream_t s1 = nullptr, s2 = nullptr;
    static cudaEvent_t eF = nullptr, eS2 = nullptr, eP1 = nullptr, eM = nullptr, eE = nullptr;
    if (!s1) {
        cudaStreamCreateWithFlags(&s1, cudaStreamNonBlocking);
        cudaStreamCreateWithFlags(&s2, cudaStreamNonBlocking);
        cudaEventCreateWithFlags(&eF,  cudaEventDisableTiming);
        cudaEventCreateWithFlags(&eS2, cudaEventDisableTiming);
        cudaEventCreateWithFlags(&eP1, cudaEventDisableTiming);
        cudaEventCreateWithFlags(&eM,  cudaEventDisableTiming);
        cudaEventCreateWithFlags(&eE,  cudaEventDisableTiming);
    }

    // fork from capture (default) stream
    cudaEventRecord(eF, 0);
    cudaStreamWaitEvent(s1, eF, 0);
    cudaStreamWaitEvent(s2, eF, 0);

    // s2: H memset + weight splits for qkv / out-proj / ew (all input-only)
    cudaMemsetAsync(H, 0, (size_t)Nn * Nn * sizeof(float), s2);
    do_split_s(in_w,  wqh, wql, (size_t)3 * Dd * Dd, s2);
    do_split_s(out_w, woh, wol, (size_t)Dd * Dd, s2);
    do_split_s(ew_w1, weh, wel, (size_t)(Dd / 2) * Dd, s2);
    cudaEventRecord(eS2, s2);

    // s1: modality-1 projection chain (independent buffers)
    do_split_s(x1,   a1h,  a1l,  (size_t)Nn * Dd, s1);
    do_split_s(w_p1, wp1h, wp1l, (size_t)Dd * Dd, s1);
    tgemm<1, 1><<<dim3(Dd / 128, Nn / 128), 128, 0, s1>>>(a1h, a1l, wp1h, wp1l, b_p1, seq + Dd, 2 * Dd);
    cudaEventRecord(eP1, s1);

    // stream 0: modality-0 projection chain (runs concurrently with s1/s2)
    do_split_s(x0,   ah,   al,   (size_t)Nn * Dd, 0);
    do_split_s(w_p0, wp0h, wp0l, (size_t)Dd * Dd, 0);
    tgemm<1, 1><<<dim3(Dd / 128, Nn / 128), 128>>>(ah, al, wp0h, wp0l, b_p0, seq, 2 * Dd);

    // join proj1 + weight splits, then trunk on stream 0
    cudaStreamWaitEvent(0, eP1, 0);
    ln_kernel<<<2 * Nn, 256>>>(gg0, be0, gg1, be1);
    cudaStreamWaitEvent(0, eS2, 0);
    tgemm<0, 1><<<dim3(3 * Dd / 128, 2 * Nn / 128), 128>>>(ah, al, wqh, wql, in_b, qkv, 3 * Dd);
    attn_kernel<<<(Nn * NHEADS * 32) / 256, 256>>>();
    tgemm<0, 1><<<dim3(Dd / 128, 2 * Nn / 128), 128>>>(ah, al, woh, wol, out_b, att, Dd);
    mean_kernel<<<(Nn * Dd / 4 + 255) / 256, 256>>>();
    cudaEventRecord(eM, 0);

    // s1: edge-weight MLP (parallel to sim GEMM + topk)
    cudaStreamWaitEvent(s1, eM, 0);
    tgemm<1, 1><<<dim3((Dd / 2) / 128, Nn / 128), 128, 0, s1>>>(fh, fl, weh, wel, ew_b1, hidden, Dd / 2);
    ew_kernel<<<(Nn * 32) / 256, 256, 0, s1>>>(ew_w2, ew_b2, ew);
    cudaEventRecord(eE, s1);

    // stream 0: similarity GEMM (symmetric) + softmax/topk/scatter
    tgemm_sym<<<(Nn / 128) * (Nn / 128 + 1) / 2, 128>>>(fh, fl, S);
    topk_kernel<<<Nn, 256, (Nn + 256) * sizeof(float)>>>(H);

    // join ew branch back into capture stream
    cudaStreamWaitEvent(0, eE, 0);
}

// round 12
// speedup vs baseline: 2.0408x; 1.2932x over previous
#include <cuda_runtime.h>
#include <cuda_fp16.h>
#include <math.h>
#include <stdint.h>

#define Nn 8192
#define Dd 512
#define KDIM 512
#define NHEADS 8
#define HDIM 64
#define TOPK 16

// ---------------- scratch (static device globals; no allocation) -------------
__device__ float g_seq[2 * Nn * Dd];
__device__ float g_qkv[2 * Nn * 3 * Dd];
__device__ float g_att[2 * Nn * Dd];
__device__ float g_S[(size_t)Nn * Nn];
__device__ float g_hidden[Nn * (Dd / 2)];
__device__ uint16_t g_ah[2 * Nn * Dd];        // activations (fp16)
__device__ uint16_t g_a1h[Nn * Dd];           // proj1 act
__device__ uint16_t g_wp0h[Dd * Dd];
__device__ uint16_t g_wp1h[Dd * Dd];
__device__ uint16_t g_wqh[3 * Dd * Dd];
__device__ uint16_t g_woh[Dd * Dd];
__device__ uint16_t g_weh[(Dd / 2) * Dd];
__device__ uint16_t g_fh[Nn * Dd];            // fused (fp16)

// ============================ PTX helpers ====================================
__device__ __forceinline__ uint32_t smem_u32(const void* p) {
    uint32_t a;
    asm("{ .reg .u64 t; cvta.to.shared.u64 t, %1; cvt.u32.u64 %0, t; }" : "=r"(a) : "l"(p));
    return a;
}
__device__ __forceinline__ void cp16(uint32_t dst, const void* src) {
    asm volatile("cp.async.cg.shared.global [%0], [%1], 16;" :: "r"(dst), "l"(src) : "memory");
}
__device__ __forceinline__ void cp_commit() {
    asm volatile("cp.async.commit_group;" ::: "memory");
}
template <int N> __device__ __forceinline__ void cp_wait() {
    asm volatile("cp.async.wait_group %0;" :: "n"(N) : "memory");
}
__device__ __forceinline__ void ldsm4(uint32_t* r, uint32_t a) {
    asm volatile("ldmatrix.sync.aligned.m8n8.x4.shared.b16 {%0,%1,%2,%3}, [%4];"
                 : "=r"(r[0]), "=r"(r[1]), "=r"(r[2]), "=r"(r[3]) : "r"(a));
}
__device__ __forceinline__ void mma16816(float* c, const uint32_t* a, uint32_t b0, uint32_t b1) {
    asm volatile("mma.sync.aligned.m16n8k16.row.col.f32.f16.f16.f32 "
                 "{%0,%1,%2,%3}, {%4,%5,%6,%7}, {%8,%9}, {%0,%1,%2,%3};"
                 : "+f"(c[0]), "+f"(c[1]), "+f"(c[2]), "+f"(c[3])
                 : "r"(a[0]), "r"(a[1]), "r"(a[2]), "r"(a[3]), "r"(b0), "r"(b1));
}

// ======================= warp-MMA NT GEMM (fp16, fp32 acc) ===================
// C[M,N] = A*B^T (single pass, pure fp16 operands).  K == 512 everywhere.
// Tile 128x128, BK=32, double-buffered cp.async, 4 warps 2x2 (64x64 per warp).
template <int RELU, int HAS_BIAS>
__global__ __launch_bounds__(128, 2) void tgemm(
    const uint16_t* __restrict__ Ap, const uint16_t* __restrict__ Bp,
    const float* __restrict__ bias, float* __restrict__ C, int ldc)
{
    __shared__ uint16_t sA[2][128 * 32];
    __shared__ uint16_t sB[2][128 * 32];

    const int tid = threadIdx.x;
    const int lane = tid & 31, wid = tid >> 5;
    const int wm = wid & 1;
    const int wn = wid >> 1;
    const int bm = blockIdx.y * 128, bn = blockIdx.x * 128;

    const uint32_t sa0 = smem_u32(&sA[0][0]), sa1 = smem_u32(&sA[1][0]);
    const uint32_t sb0 = smem_u32(&sB[0][0]), sb1 = smem_u32(&sB[1][0]);

    const int NCHK = KDIM / 32;      // 16

    uint32_t lsw[4]; size_t lsrc[4];
#pragma unroll
    for (int i = 0; i < 4; i++) {
        int s = tid + 128 * i;
        int r = s >> 2, c = s & 3;
        lsw[i] = r * 64 + (((c ^ ((r >> 1) & 3))) << 4);
        lsrc[i] = (size_t)r * KDIM + c * 8;
    }

    uint32_t offA[2][4], offB[2][4];
#pragma unroll
    for (int kk = 0; kk < 2; kk++) {
#pragma unroll
        for (int f = 0; f < 4; f++) {
            int r = wm * 64 + f * 16 + (lane & 15);
            int c = kk * 2 + (lane >> 4);
            offA[kk][f] = r * 64 + (((c ^ ((r >> 1) & 3))) << 4);
        }
#pragma unroll
        for (int g = 0; g < 4; g++) {
            int r = wn * 64 + g * 16 + (lane & 7) + ((lane >> 4) << 3);
            int c = kk * 2 + ((lane >> 3) & 1);
            offB[kk][g] = r * 64 + (((c ^ ((r >> 1) & 3))) << 4);
        }
    }

    float acc[4][8][4];
#pragma unroll
    for (int f = 0; f < 4; f++)
#pragma unroll
        for (int g = 0; g < 8; g++)
#pragma unroll
            for (int j = 0; j < 4; j++) acc[f][g][j] = 0.f;

    auto load_chunk = [&](int c, int buf) {
        const int k0 = c * 32;
        const uint32_t da = buf ? sa1 : sa0;
        const uint32_t db = buf ? sb1 : sb0;
#pragma unroll
        for (int i = 0; i < 4; i++) {
            cp16(da + lsw[i], Ap + (size_t)bm * KDIM + k0 + lsrc[i]);
            cp16(db + lsw[i], Bp + (size_t)bn * KDIM + k0 + lsrc[i]);
        }
        cp_commit();
    };

    load_chunk(0, 0);

    for (int c = 0; c < NCHK; c++) {
        const int b = c & 1;
        if (c + 1 < NCHK) { load_chunk(c + 1, b ^ 1); cp_wait<1>(); }
        else cp_wait<0>();
        __syncthreads();

        const uint32_t da = b ? sa1 : sa0;
        const uint32_t db = b ? sb1 : sb0;
#pragma unroll
        for (int kk = 0; kk < 2; kk++) {
            uint32_t ra[4][4], rb[4][4];
#pragma unroll
            for (int f = 0; f < 4; f++) ldsm4(ra[f], da + offA[kk][f]);
#pragma unroll
            for (int g = 0; g < 4; g++) ldsm4(rb[g], db + offB[kk][g]);
#pragma unroll
            for (int f = 0; f < 4; f++)
#pragma unroll
                for (int g = 0; g < 4; g++) {
                    mma16816(acc[f][2 * g + 0], ra[f], rb[g][0], rb[g][1]);
                    mma16816(acc[f][2 * g + 1], ra[f], rb[g][2], rb[g][3]);
                }
        }
        __syncthreads();
    }

    const int col0 = bn + wn * 64 + (lane & 3) * 2;
#pragma unroll
    for (int f = 0; f < 4; f++) {
        const int row0 = bm + wm * 64 + f * 16 + (lane >> 2);
#pragma unroll
        for (int g = 0; g < 8; g++) {
            const int col = col0 + g * 8;
            float b0 = 0.f, b1 = 0.f;
            if (HAS_BIAS) { b0 = bias[col]; b1 = bias[col + 1]; }
            float2 v0, v1;
            v0.x = acc[f][g][0] + b0; v0.y = acc[f][g][1] + b1;
            v1.x = acc[f][g][2] + b0; v1.y = acc[f][g][3] + b1;
            if (RELU) {
                v0.x = fmaxf(v0.x, 0.f); v0.y = fmaxf(v0.y, 0.f);
                v1.x = fmaxf(v1.x, 0.f); v1.y = fmaxf(v1.y, 0.f);
            }
            *(float2*)(C + (size_t)row0 * ldc + col) = v0;
            *(float2*)(C + (size_t)(row0 + 8) * ldc + col) = v1;
        }
    }
}

// ============== symmetric variant: S = F*F^T, upper-triangle blocks ==========
__global__ __launch_bounds__(128, 2) void tgemm_sym(
    const uint16_t* __restrict__ Fp, float* __restrict__ C)
{
    __shared__ __align__(16) uint8_t smraw[32768];
    uint16_t* sAbase = (uint16_t*)smraw;
    uint16_t* sBbase = (uint16_t*)(smraw + 16384);
    float* smT = (float*)smraw;

    const int tid = threadIdx.x;
    const int lane = tid & 31, wid = tid >> 5;
    const int wm = wid & 1;
    const int wn = wid >> 1;

    int t = blockIdx.x;
    int bj = (int)((sqrtf(8.f * t + 1.f) - 1.f) * 0.5f);
    while ((bj + 1) * (bj + 2) / 2 <= t) bj++;
    while (bj * (bj + 1) / 2 > t) bj--;
    int bi = t - bj * (bj + 1) / 2;
    const int bm = bi * 128, bn = bj * 128;

    const uint32_t sa0 = smem_u32(sAbase), sa1 = smem_u32(sAbase + 4096);
    const uint32_t sb0 = smem_u32(sBbase), sb1 = smem_u32(sBbase + 4096);

    const int NCHK = KDIM / 32;

    uint32_t lsw[4]; size_t lsrc[4];
#pragma unroll
    for (int i = 0; i < 4; i++) {
        int s = tid + 128 * i;
        int r = s >> 2, c = s & 3;
        lsw[i] = r * 64 + (((c ^ ((r >> 1) & 3))) << 4);
        lsrc[i] = (size_t)r * KDIM + c * 8;
    }

    uint32_t offA[2][4], offB[2][4];
#pragma unroll
    for (int kk = 0; kk < 2; kk++) {
#pragma unroll
        for (int f = 0; f < 4; f++) {
            int r = wm * 64 + f * 16 + (lane & 15);
            int c = kk * 2 + (lane >> 4);
            offA[kk][f] = r * 64 + (((c ^ ((r >> 1) & 3))) << 4);
        }
#pragma unroll
        for (int g = 0; g < 4; g++) {
            int r = wn * 64 + g * 16 + (lane & 7) + ((lane >> 4) << 3);
            int c = kk * 2 + ((lane >> 3) & 1);
            offB[kk][g] = r * 64 + (((c ^ ((r >> 1) & 3))) << 4);
        }
    }

    float acc[4][8][4];
#pragma unroll
    for (int f = 0; f < 4; f++)
#pragma unroll
        for (int g = 0; g < 8; g++)
#pragma unroll
            for (int j = 0; j < 4; j++) acc[f][g][j] = 0.f;

    auto load_chunk = [&](int c, int buf) {
        const int k0 = c * 32;
        const uint32_t da = buf ? sa1 : sa0;
        const uint32_t db = buf ? sb1 : sb0;
#pragma unroll
        for (int i = 0; i < 4; i++) {
            cp16(da + lsw[i], Fp + (size_t)bm * KDIM + k0 + lsrc[i]);
            cp16(db + lsw[i], Fp + (size_t)bn * KDIM + k0 + lsrc[i]);
        }
        cp_commit();
    };

    load_chunk(0, 0);

    for (int c = 0; c < NCHK; c++) {
        const int b = c & 1;
        if (c + 1 < NCHK) { load_chunk(c + 1, b ^ 1); cp_wait<1>(); }
        else cp_wait<0>();
        __syncthreads();

        const uint32_t da = b ? sa1 : sa0;
        const uint32_t db = b ? sb1 : sb0;
#pragma unroll
        for (int kk = 0; kk < 2; kk++) {
            uint32_t ra[4][4], rb[4][4];
#pragma unroll
            for (int f = 0; f < 4; f++) ldsm4(ra[f], da + offA[kk][f]);
#pragma unroll
            for (int g = 0; g < 4; g++) ldsm4(rb[g], db + offB[kk][g]);
#pragma unroll
            for (int f = 0; f < 4; f++)
#pragma unroll
                for (int g = 0; g < 4; g++) {
                    mma16816(acc[f][2 * g + 0], ra[f], rb[g][0], rb[g][1]);
                    mma16816(acc[f][2 * g + 1], ra[f], rb[g][2], rb[g][3]);
                }
        }
        __syncthreads();
    }

    // normal (upper) tile write
    const int col0 = bn + wn * 64 + (lane & 3) * 2;
#pragma unroll
    for (int f = 0; f < 4; f++) {
        const int row0 = bm + wm * 64 + f * 16 + (lane >> 2);
#pragma unroll
        for (int g = 0; g < 8; g++) {
            const int col = col0 + g * 8;
            float2 v0, v1;
            v0.x = acc[f][g][0]; v0.y = acc[f][g][1];
            v1.x = acc[f][g][2]; v1.y = acc[f][g][3];
            *(float2*)(C + (size_t)row0 * Nn + col) = v0;
            *(float2*)(C + (size_t)(row0 + 8) * Nn + col) = v1;
        }
    }

    // mirrored (lower) tile write via smem transpose, coalesced
    if (bi != bj) {
#pragma unroll
        for (int cc = 0; cc < 2; cc++) {
            __syncthreads();
            float* buf = smT + wn * (32 * 128);
#pragma unroll
            for (int gl = 0; gl < 4; gl++) {
                const int g = cc * 4 + gl;
                const int cl = gl * 8 + (lane & 3) * 2;
#pragma unroll
                for (int f = 0; f < 4; f++) {
                    const int r = wm * 64 + f * 16 + (lane >> 2);
                    buf[cl * 128 + r]           = acc[f][g][0];
                    buf[(cl + 1) * 128 + r]     = acc[f][g][1];
                    buf[cl * 128 + r + 8]       = acc[f][g][2];
                    buf[(cl + 1) * 128 + r + 8] = acc[f][g][3];
                }
            }
            __syncthreads();
            for (int idx = tid; idx < 64 * 32; idx += 128) {
                const int rr = idx >> 5;
                const int sg = idx & 31;
                const int b2 = rr >> 5;
                const int cl = rr & 31;
                const int cAbs = bn + b2 * 64 + cc * 32 + cl;
                float4 v = *(float4*)(smT + b2 * (32 * 128) + cl * 128 + sg * 4);
                *(float4*)(C + (size_t)cAbs * Nn + bm + sg * 4) = v;
            }
        }
    }
}

// ---------------- fp32 -> fp16 convert ---------------------------------------
__global__ void split_kernel(const float* __restrict__ x, uint16_t* __restrict__ hi,
                             int n4)
{
    int i = blockIdx.x * blockDim.x + threadIdx.x;
    if (i >= n4) return;
    float4 v = ((const float4*)x)[i];
    ushort4 hv;
    hv.x = __half_as_ushort(__float2half_rn(v.x));
    hv.y = __half_as_ushort(__float2half_rn(v.y));
    hv.z = __half_as_ushort(__float2half_rn(v.z));
    hv.w = __half_as_ushort(__float2half_rn(v.w));
    ((ushort4*)hi)[i] = hv;
}

// ---------------- LayerNorm -> fp16 directly ---------------------------------
__global__ void ln_kernel(const float* __restrict__ g0, const float* __restrict__ be0,
                          const float* __restrict__ g1, const float* __restrict__ be1)
{
    int row = blockIdx.x;
    const float* x = g_seq + (size_t)row * Dd;
    int tid = threadIdx.x;
    float v0 = x[tid], v1 = x[tid + 256];
    __shared__ float rs[256], rq[256];
    rs[tid] = v0 + v1;
    rq[tid] = v0 * v0 + v1 * v1;
    __syncthreads();
    for (int st = 128; st > 0; st >>= 1) {
        if (tid < st) { rs[tid] += rs[tid + st]; rq[tid] += rq[tid + st]; }
        __syncthreads();
    }
    float mean = rs[0] * (1.f / Dd);
    float var = rq[0] * (1.f / Dd) - mean * mean;
    float inv = rsqrtf(var + 1e-5f);
    const float* gg = (row & 1) ? g1 : g0;
    const float* bb = (row & 1) ? be1 : be0;
    float y0 = (v0 - mean) * inv * gg[tid] + bb[tid];
    float y1 = (v1 - mean) * inv * gg[tid + 256] + bb[tid + 256];
    size_t base = (size_t)row * Dd;
    g_ah[base + tid]       = __half_as_ushort(__float2half_rn(y0));
    g_ah[base + tid + 256] = __half_as_ushort(__float2half_rn(y1));
}

// ---------------- 2-token multihead attention -> ctx fp16 --------------------
__global__ void attn_kernel()
{
    int gt = blockIdx.x * blockDim.x + threadIdx.x;
    int gw = gt >> 5, lane = gt & 31;
    if (gw >= Nn * NHEADS) return;
    int node = gw >> 3, h = gw & 7;
    const float* base = g_qkv + (size_t)node * 2 * (3 * Dd);
    int d0 = lane * 2;
    float q[2][2], k[2][2], v[2][2];
#pragma unroll
    for (int t = 0; t < 2; t++) {
        const float* r = base + t * (3 * Dd) + h * HDIM;
        float2 qq = *(const float2*)(r + d0);
        float2 kk = *(const float2*)(r + Dd + d0);
        float2 vv = *(const float2*)(r + 2 * Dd + d0);
        q[t][0] = qq.x; q[t][1] = qq.y;
        k[t][0] = kk.x; k[t][1] = kk.y;
        v[t][0] = vv.x; v[t][1] = vv.y;
    }
    float s[2][2];
#pragma unroll
    for (int qi = 0; qi < 2; qi++)
#pragma unroll
        for (int ki = 0; ki < 2; ki++)
            s[qi][ki] = q[qi][0] * k[ki][0] + q[qi][1] * k[ki][1];
#pragma unroll
    for (int o = 16; o > 0; o >>= 1)
#pragma unroll
        for (int qi = 0; qi < 2; qi++)
#pragma unroll
            for (int ki = 0; ki < 2; ki++)
                s[qi][ki] += __shfl_xor_sync(0xffffffffu, s[qi][ki], o);
    const float scale = 0.125f;
#pragma unroll
    for (int qi = 0; qi < 2; qi++) {
        float a0 = s[qi][0] * scale, a1 = s[qi][1] * scale;
        float m = fmaxf(a0, a1);
        float e0 = expf(a0 - m), e1 = expf(a1 - m);
        float inv = 1.f / (e0 + e1);
        float w0 = e0 * inv, w1 = e1 * inv;
        float o0 = w0 * v[0][0] + w1 * v[1][0];
        float o1 = w0 * v[0][1] + w1 * v[1][1];
        size_t off = (size_t)(node * 2 + qi) * Dd + h * HDIM + d0;
        ushort2 hv;
        hv.x = __half_as_ushort(__float2half_rn(o0));
        hv.y = __half_as_ushort(__float2half_rn(o1));
        *(ushort2*)(g_ah + off) = hv;
    }
}

// ---------------- mean over the 2 tokens -> fused fp16 -----------------------
__global__ void mean_kernel()
{
    int i = blockIdx.x * blockDim.x + threadIdx.x;
    if (i >= Nn * Dd / 4) return;
    int e0 = i * 4;
    int node = e0 / Dd, d = e0 - node * Dd;
    const float* r0 = g_att + (size_t)(node * 2) * Dd + d;
    const float* r1 = g_att + (size_t)(node * 2 + 1) * Dd + d;
    float4 a = *(const float4*)r0, b = *(const float4*)r1;
    ushort4 hv;
    hv.x = __half_as_ushort(__float2half_rn(0.5f * (a.x + b.x)));
    hv.y = __half_as_ushort(__float2half_rn(0.5f * (a.y + b.y)));
    hv.z = __half_as_ushort(__float2half_rn(0.5f * (a.z + b.z)));
    hv.w = __half_as_ushort(__float2half_rn(0.5f * (a.w + b.w)));
    ((ushort4*)g_fh)[i] = hv;
}

// ---------------- softmax stats + top-16 via segment-max hierarchy ----------
__global__ void topk_kernel(float* __restrict__ Hout)
{
    int row = blockIdx.x;
    extern __shared__ float sh[];                 // Nn floats + 256 segmax
    float* segmax = sh + Nn;
    __shared__ float swv[8];
    __shared__ int swi[8];
    __shared__ float s_bcast;
    __shared__ int s_seg;
    __shared__ float topv[TOPK];
    __shared__ int topi[TOPK];
    const float* srow = g_S + (size_t)row * Nn;
    int tid = threadIdx.x;
    int lane = tid & 31, wid = tid >> 5;

    for (int j = tid; j < Nn; j += 256) sh[j] = srow[j];
    __syncthreads();

    {
        const int base = tid * 32;
        float sm = -INFINITY;
#pragma unroll 8
        for (int i = 0; i < 32; i++)
            sm = fmaxf(sm, sh[base + ((i + tid) & 31)]);
        segmax[tid] = sm;
        float lmax = sm;
#pragma unroll
        for (int o = 16; o > 0; o >>= 1)
            lmax = fmaxf(lmax, __shfl_xor_sync(0xffffffffu, lmax, o));
        if (lane == 0) swv[wid] = lmax;
    }
    __syncthreads();
    if (tid == 0) {
        float m = swv[0];
#pragma unroll
        for (int w = 1; w < 8; w++) m = fmaxf(m, swv[w]);
        s_bcast = m;
    }
    __syncthreads();
    const float rmax = s_bcast;

    float lsum = 0.f;
    for (int j = tid; j < Nn; j += 256) lsum += expf(sh[j] - rmax);
#pragma unroll
    for (int o = 16; o > 0; o >>= 1)
        lsum += __shfl_xor_sync(0xffffffffu, lsum, o);
    if (lane == 0) swv[wid] = lsum;
    __syncthreads();
    if (tid == 0) {
        float s = 0.f;
#pragma unroll
        for (int w = 0; w < 8; w++) s += swv[w];
        s_bcast = 1.f / s;
    }
    __syncthreads();
    const float rinv = s_bcast;

    for (int kk = 0; kk < TOPK; kk++) {
        float v = segmax[tid];
        int idx = tid;
#pragma unroll
        for (int o = 16; o > 0; o >>= 1) {
            float ov = __shfl_xor_sync(0xffffffffu, v, o);
            int oi = __shfl_xor_sync(0xffffffffu, idx, o);
            if (ov > v || (ov == v && oi < idx)) { v = ov; idx = oi; }
        }
        if (lane == 0) { swv[wid] = v; swi[wid] = idx; }
        __syncthreads();
        if (tid == 0) {
            float bv = swv[0]; int bi = swi[0];
#pragma unroll
            for (int w = 1; w < 8; w++)
                if (swv[w] > bv || (swv[w] == bv && swi[w] < bi)) { bv = swv[w]; bi = swi[w]; }
            s_seg = bi;
        }
        __syncthreads();
        const int s = s_seg;
        if (wid == 0) {
            int ei = s * 32 + lane;
            float ev = sh[ei];
            float v2 = ev; int i2 = ei;
#pragma unroll
            for (int o = 16; o > 0; o >>= 1) {
                float ov = __shfl_xor_sync(0xffffffffu, v2, o);
                int oi = __shfl_xor_sync(0xffffffffu, i2, o);
                if (ov > v2 || (ov == v2 && oi < i2)) { v2 = ov; i2 = oi; }
            }
            if (lane == 0) { topv[kk] = v2; topi[kk] = i2; }
            float nv = (ei == i2) ? -INFINITY : ev;
            if (ei == i2) sh[ei] = -INFINITY;
            float mx = nv;
#pragma unroll
            for (int o = 16; o > 0; o >>= 1)
                mx = fmaxf(mx, __shfl_xor_sync(0xffffffffu, mx, o));
            if (lane == 0) segmax[s] = mx;
        }
        __syncthreads();
    }

    if (tid == 0) {
        Hout[(size_t)row * Nn + row] = 1.0f;
#pragma unroll
        for (int kk = 0; kk < TOPK; kk++)
            Hout[(size_t)topi[kk] * Nn + row] = expf(topv[kk] - rmax) * rinv;
    }
}

__global__ void ew_kernel(const float* __restrict__ w2, const float* __restrict__ b2,
                          float* __restrict__ out)
{
    int gt = blockIdx.x * blockDim.x + threadIdx.x;
    int gw = gt >> 5, lane = gt & 31;
    if (gw >= Nn) return;
    const float* hrow = g_hidden + (size_t)gw * (Dd / 2);
    float s = 0.f;
    for (int j = lane; j < Dd / 2; j += 32) s += hrow[j] * w2[j];
#pragma unroll
    for (int o = 16; o > 0; o >>= 1) s += __shfl_xor_sync(0xffffffffu, s, o);
    if (lane == 0) {
        float v = s + b2[0];
        float sig = 1.f / (1.f + expf(-v));
        out[gw] = fmaxf(sig, 1e-8f);
    }
}

// ---------------- launch ------------------------------------------------------
static void do_split_s(const float* src, uint16_t* hi, size_t n, cudaStream_t st)
{
    int n4 = (int)(n / 4);
    split_kernel<<<(n4 + 255) / 256, 256, 0, st>>>(src, hi, n4);
}

extern "C" void kernel_launch(void* const* d_in, const int* in_sizes, int n_in,
                              void* d_out, int out_size)
{
    const float* x0    = (const float*)d_in[0];
    const float* x1    = (const float*)d_in[1];
    const float* w_p0  = (const float*)d_in[2];
    const float* b_p0  = (const float*)d_in[3];
    const float* gg0   = (const float*)d_in[4];
    const float* be0   = (const float*)d_in[5];
    const float* w_p1  = (const float*)d_in[6];
    const float* b_p1  = (const float*)d_in[7];
    const float* gg1   = (const float*)d_in[8];
    const float* be1   = (const float*)d_in[9];
    const float* in_w  = (const float*)d_in[10];
    const float* in_b  = (const float*)d_in[11];
    const float* out_w = (const float*)d_in[12];
    const float* out_b = (const float*)d_in[13];
    const float* ew_w1 = (const float*)d_in[14];
    const float* ew_b1 = (const float*)d_in[15];
    const float* ew_w2 = (const float*)d_in[16];
    const float* ew_b2 = (const float*)d_in[17];

    float* H  = (float*)d_out;
    float* ew = H + (size_t)Nn * Nn;

    float *seq, *qkv, *att, *S, *hidden;
    uint16_t *ah, *a1h, *fh;
    uint16_t *wp0h, *wp1h, *wqh, *woh, *weh;
    cudaGetSymbolAddress((void**)&seq, g_seq);
    cudaGetSymbolAddress((void**)&qkv, g_qkv);
    cudaGetSymbolAddress((void**)&att, g_att);
    cudaGetSymbolAddress((void**)&S, g_S);
    cudaGetSymbolAddress((void**)&hidden, g_hidden);
    cudaGetSymbolAddress((void**)&ah, g_ah);
    cudaGetSymbolAddress((void**)&a1h, g_a1h);
    cudaGetSymbolAddress((void**)&wp0h, g_wp0h);
    cudaGetSymbolAddress((void**)&wp1h, g_wp1h);
    cudaGetSymbolAddress((void**)&wqh, g_wqh);
    cudaGetSymbolAddress((void**)&woh, g_woh);
    cudaGetSymbolAddress((void**)&weh, g_weh);
    cudaGetSymbolAddress((void**)&fh, g_fh);

    // streams/events created ONCE (first call = correctness run, inside the
    // harness's pre-capture baseline) and reused on every later call.
    static cudaStream_t s1 = nullptr, s2 = nullptr;
    static cudaEvent_t eF = nullptr, eS2 = nullptr, eP1 = nullptr, eM = nullptr, eE = nullptr;
    if (!s1) {
        cudaStreamCreateWithFlags(&s1, cudaStreamNonBlocking);
        cudaStreamCreateWithFlags(&s2, cudaStreamNonBlocking);
        cudaEventCreateWithFlags(&eF,  cudaEventDisableTiming);
        cudaEventCreateWithFlags(&eS2, cudaEventDisableTiming);
        cudaEventCreateWithFlags(&eP1, cudaEventDisableTiming);
        cudaEventCreateWithFlags(&eM,  cudaEventDisableTiming);
        cudaEventCreateWithFlags(&eE,  cudaEventDisableTiming);
    }

    // fork from capture (default) stream
    cudaEventRecord(eF, 0);
    cudaStreamWaitEvent(s1, eF, 0);
    cudaStreamWaitEvent(s2, eF, 0);

    // s2: H memset + weight converts for qkv / out-proj / ew (input-only)
    cudaMemsetAsync(H, 0, (size_t)Nn * Nn * sizeof(float), s2);
    do_split_s(in_w,  wqh, (size_t)3 * Dd * Dd, s2);
    do_split_s(out_w, woh, (size_t)Dd * Dd, s2);
    do_split_s(ew_w1, weh, (size_t)(Dd / 2) * Dd, s2);
    cudaEventRecord(eS2, s2);

    // s1: modality-1 projection chain (independent buffers)
    do_split_s(x1,   a1h,  (size_t)Nn * Dd, s1);
    do_split_s(w_p1, wp1h, (size_t)Dd * Dd, s1);
    tgemm<1, 1><<<dim3(Dd / 128, Nn / 128), 128, 0, s1>>>(a1h, wp1h, b_p1, seq + Dd, 2 * Dd);
    cudaEventRecord(eP1, s1);

    // stream 0: modality-0 projection chain (concurrent with s1/s2)
    do_split_s(x0,   ah,   (size_t)Nn * Dd, 0);
    do_split_s(w_p0, wp0h, (size_t)Dd * Dd, 0);
    tgemm<1, 1><<<dim3(Dd / 128, Nn / 128), 128>>>(ah, wp0h, b_p0, seq, 2 * Dd);

    // join proj1 + weight converts, then trunk on stream 0
    cudaStreamWaitEvent(0, eP1, 0);
    ln_kernel<<<2 * Nn, 256>>>(gg0, be0, gg1, be1);
    cudaStreamWaitEvent(0, eS2, 0);
    tgemm<0, 1><<<dim3(3 * Dd / 128, 2 * Nn / 128), 128>>>(ah, wqh, in_b, qkv, 3 * Dd);
    attn_kernel<<<(Nn * NHEADS * 32) / 256, 256>>>();
    tgemm<0, 1><<<dim3(Dd / 128, 2 * Nn / 128), 128>>>(ah, woh, out_b, att, Dd);
    mean_kernel<<<(Nn * Dd / 4 + 255) / 256, 256>>>();
    cudaEventRecord(eM, 0);

    // s1: edge-weight MLP (parallel to sim GEMM + topk)
    cudaStreamWaitEvent(s1, eM, 0);
    tgemm<1, 1><<<dim3((Dd / 2) / 128, Nn / 128), 128, 0, s1>>>(fh, weh, ew_b1, hidden, Dd / 2);
    ew_kernel<<<(Nn * 32) / 256, 256, 0, s1>>>(ew_w2, ew_b2, ew);
    cudaEventRecord(eE, s1);

    // stream 0: similarity GEMM (symmetric) + softmax/topk/scatter
    tgemm_sym<<<(Nn / 128) * (Nn / 128 + 1) / 2, 128>>>(fh, S);
    topk_kernel<<<Nn, 256, (Nn + 256) * sizeof(float)>>>(H);

    // join ew branch back into capture stream
    cudaStreamWaitEvent(0, eE, 0);
}